// round 1
// baseline (speedup 1.0000x reference)
#include <cuda_runtime.h>
#include <math.h>

#define TLEN    160000
#define NBATCH  64
#define NFRAMES 624
#define NBANDS  49
#define CHUNK   3200
#define NCH     (TLEN/CHUNK)   // 50
#define FULLM   0xffffffffu

// ---------------- persistent device buffers (no allocation allowed) ----------
__device__ float g_filt[2][NBATCH][TLEN];           // 0 = ref (from deg_in), 1 = deg (from ref_in)
__device__ float g_bark[2][NBATCH][NFRAMES][NBANDS];
__device__ int   g_silent[NBATCH][NFRAMES];
__device__ int   g_cnt[NBATCH];
__device__ float g_bpr[NBATCH][NBANDS];
__device__ float g_fpr0[NBATCH][NFRAMES];
__device__ float g_taeq[NBATCH][NFRAMES];
__device__ float g_symm[NBATCH][NFRAMES];
__device__ float g_asym[NBATCH][NFRAMES];

// ---------------- tables (filled by k_init each launch) ----------------------
__device__ float d_hw[1024][2];    // A^d * c   (warmup impulse response of state)
__device__ float d_g64[64][2];     // A^{-1-i} * c
__device__ float d_r064[64][2];    // row 0 of A^m
__device__ float d_A64[4];         // A^64
__device__ int   d_band[256];
__device__ float d_powcorr[NBANDS];
__device__ float d_thresh[NBANDS];
__device__ float d_g023[NBANDS];   // (th/0.5)^0.23
__device__ float d_hann[512];
__device__ float d_w0, d_wsum;

__device__ __forceinline__ float wredsum(float v) {
    #pragma unroll
    for (int o = 16; o; o >>= 1) v += __shfl_xor_sync(FULLM, v, o);
    return v;
}

// ============================ table init =====================================
__global__ void k_init() {
    int t = threadIdx.x;
    __shared__ int s_cnt[NBANDS];
    if (t < NBANDS) s_cnt[t] = 0;
    __syncthreads();

    const double maxbark = 7.0 * asinh(8000.0 / 650.0);
    const double step = maxbark / 49.0;

    if (t < 256) {
        double f = (t + 0.5) * (16000.0 / 512.0);
        double bark = 7.0 * asinh(f / 650.0);
        int idx = 0;
        for (int j = 0; j <= 49; j++) {
            double e = (j == 49) ? maxbark : step * j;
            if (e <= bark) idx = j + 1;
        }
        int band = idx - 1;
        band = min(max(band, 0), 48);
        d_band[t] = band;
        atomicAdd(&s_cnt[band], 1);
    }
    if (t < 512)
        d_hann[t] = (float)(0.5 - 0.5 * cos(2.0 * 3.141592653589793 * t / 512.0));
    __syncthreads();

    if (t < NBANDS) {
        double cnt = s_cnt[t] > 1 ? (double)s_cnt[t] : 1.0;
        d_powcorr[t] = (float)(6.910853e-6 * 100.0 / cnt);
        double e0 = step * t;
        double e1 = (t == 48) ? maxbark : step * (t + 1);
        double fc = 650.0 * sinh(0.5 * (e0 + e1) / 7.0);
        if (fc < 20.0) fc = 20.0;
        fc /= 1000.0;
        double ath = 3.64 * pow(fc, -0.8) - 6.5 * exp(-0.6 * (fc - 3.3) * (fc - 3.3)) + 1e-3 * pow(fc, 4.0);
        double th = pow(10.0, ath / 10.0);
        d_thresh[t] = (float)th;
        d_g023[t] = (float)pow(th / 0.5, 0.23);
    }
    if (t == 0) {
        float w0f = (float)step;
        float ws = 0.f;
        for (int i = 0; i < 49; i++) ws += w0f;
        d_w0 = w0f; d_wsum = ws;

        const double b0 = 2.740826, b1 = -5.4816519, b2 = 2.740826;
        const double a1 = -1.9444777, a2 = 0.94597794;
        double A00 = -a1, A01 = 1.0, A10 = -a2, A11 = 0.0;
        double c0 = b1 - a1 * b0, c1 = b2 - a2 * b0;

        // hw[d] = A^d c
        double v0 = c0, v1 = c1;
        for (int d = 0; d < 1024; d++) {
            d_hw[d][0] = (float)v0; d_hw[d][1] = (float)v1;
            double n0 = A00 * v0 + A01 * v1, n1 = A10 * v0 + A11 * v1;
            v0 = n0; v1 = n1;
        }
        // A inverse
        double det = A00 * A11 - A01 * A10;   // = a2
        double I00 = A11 / det, I01 = -A01 / det, I10 = -A10 / det, I11 = A00 / det;
        // g64[i] = A^{-1-i} c
        v0 = I00 * c0 + I01 * c1; v1 = I10 * c0 + I11 * c1;
        for (int i = 0; i < 64; i++) {
            d_g64[i][0] = (float)v0; d_g64[i][1] = (float)v1;
            double n0 = I00 * v0 + I01 * v1, n1 = I10 * v0 + I11 * v1;
            v0 = n0; v1 = n1;
        }
        // r064[m] = e0^T A^m
        double r0 = 1.0, r1 = 0.0;
        for (int m = 0; m < 64; m++) {
            d_r064[m][0] = (float)r0; d_r064[m][1] = (float)r1;
            double n0 = r0 * A00 + r1 * A10, n1 = r0 * A01 + r1 * A11;
            r0 = n0; r1 = n1;
        }
        // A^64 by repeated squaring
        double M00 = A00, M01 = A01, M10 = A10, M11 = A11;
        for (int k = 0; k < 6; k++) {
            double n00 = M00 * M00 + M01 * M10, n01 = M00 * M01 + M01 * M11;
            double n10 = M10 * M00 + M11 * M10, n11 = M10 * M01 + M11 * M11;
            M00 = n00; M01 = n01; M10 = n10; M11 = n11;
        }
        d_A64[0] = (float)M00; d_A64[1] = (float)M01;
        d_A64[2] = (float)M10; d_A64[3] = (float)M11;
    }
}

__global__ void k_zero() {
    int t = threadIdx.x;
    if (t < NBATCH) g_cnt[t] = 0;
}

// ============================ IIR (warp-parallel affine scan) ================
// state recurrence: s[t+1] = A s[t] + c x[t];  y[t] = b0 x[t] + s0[t]
// chunk start state approximated by 1024-tap warmup (pole^1024 ~ 5e-13).
__global__ void k_iir(const float* __restrict__ deg_in, const float* __restrict__ ref_in) {
    int gw = (blockIdx.x * blockDim.x + threadIdx.x) >> 5;
    int lane = threadIdx.x & 31;
    int sig = gw / NCH;
    int ch = gw % NCH;
    if (sig >= 2 * NBATCH) return;
    int kind = sig & 1;
    int b = sig >> 1;
    const float* src = (kind == 0) ? deg_in + (size_t)b * TLEN : ref_in + (size_t)b * TLEN;
    const float scale = (kind == 0) ? 32320.01953125f : 23455.2265625f;
    float* dst = &g_filt[kind][b][0];
    const int t0 = ch * CHUNK;

    auto ld = [&](int t) -> float {
        float v = src[t] * scale;
        if (t < 15)               v *= (float)(t + 1) * 0.0625f;
        else if (t >= TLEN - 15)  v *= (float)(TLEN - t) * 0.0625f;
        return v;
    };

    float c0 = 0.f, c1 = 0.f;
    if (t0 > 0) {
        float a0 = 0.f, a1 = 0.f;
        #pragma unroll
        for (int it = 0; it < 32; it++) {
            int d = it * 32 + lane;
            float xv = ld(t0 - 1 - d);
            a0 += d_hw[d][0] * xv;
            a1 += d_hw[d][1] * xv;
        }
        c0 = wredsum(a0);
        c1 = wredsum(a1);
    }

    const float B0 = 2.740826f;
    const float A00 = d_A64[0], A01 = d_A64[1], A10 = d_A64[2], A11 = d_A64[3];
    const int i0 = 2 * lane, i1 = 2 * lane + 1;
    const float g00 = d_g64[i0][0], g01 = d_g64[i0][1];
    const float g10 = d_g64[i1][0], g11 = d_g64[i1][1];
    const float r00 = d_r064[i0][0], r01 = d_r064[i0][1];
    const float r10 = d_r064[i1][0], r11 = d_r064[i1][1];

    for (int blk = 0; blk < CHUNK / 64; blk++) {
        int base = t0 + blk * 64;
        int ta = base + i0;
        float x0 = ld(ta), x1 = ld(ta + 1);
        float u0 = g00 * x0 + g10 * x1;
        float u1 = g01 * x0 + g11 * x1;
        float p0 = u0, p1 = u1;     // inclusive prefix
        #pragma unroll
        for (int d = 1; d < 32; d <<= 1) {
            float v0 = __shfl_up_sync(FULLM, p0, d);
            float v1 = __shfl_up_sync(FULLM, p1, d);
            if (lane >= d) { p0 += v0; p1 += v1; }
        }
        float tot0 = __shfl_sync(FULLM, p0, 31);
        float tot1 = __shfl_sync(FULLM, p1, 31);
        float e0 = p0 - u0, e1 = p1 - u1;   // exclusive prefix
        float P0 = c0 + e0, P1 = c1 + e1;
        float y0 = B0 * x0 + (r00 * P0 + r01 * P1);
        float Q0 = P0 + g00 * x0, Q1 = P1 + g01 * x0;
        float y1 = B0 * x1 + (r10 * Q0 + r11 * Q1);
        *reinterpret_cast<float2*>(dst + ta) = make_float2(y0, y1);
        float n0 = c0 + tot0, n1 = c1 + tot1;
        c0 = A00 * n0 + A01 * n1;
        c1 = A10 * n0 + A11 * n1;
    }
}

// ============================ spectrogram + bark =============================
// one 128-thread block per (frame, batch, kind). Real 512-pt FFT via
// packed 256-pt complex Stockham. Fused window, power, bin0-zero, bark sums.
__global__ void k_spec() {
    int f = blockIdx.x, b = blockIdx.y, kind = blockIdx.z;
    int t = threadIdx.x;
    __shared__ float2 za[256], zb[256];
    __shared__ float sband[NBANDS];
    const float* sigp = &g_filt[kind][b][0];
    const int base = f * 256;

    #pragma unroll
    for (int h = 0; h < 2; h++) {
        int m = t + h * 128;
        int n0 = 2 * m, n1 = 2 * m + 1;
        int s0 = base + n0, s1 = base + n1;
        if (kind == 1) { s0 = min(s0 + 1, TLEN - 1); s1 = min(s1 + 1, TLEN - 1); }
        za[m] = make_float2(sigp[s0] * d_hann[n0], sigp[s1] * d_hann[n1]);
    }
    if (t < NBANDS) sband[t] = 0.f;
    __syncthreads();

    float2* src = za;
    float2* dstp = zb;
    int ncur = 256;
    #pragma unroll
    for (int st = 0; st < 8; st++) {
        int m = ncur >> 1;
        int q = t & ((1 << st) - 1);
        int p = t >> st;
        float2 aa = src[q + (p << st)];
        float2 bb = src[q + ((p + m) << st)];
        float sn, cs;
        sincospif(-2.0f * (float)p / (float)ncur, &sn, &cs);
        float dx = aa.x - bb.x, dy = aa.y - bb.y;
        dstp[q + ((2 * p) << st)]     = make_float2(aa.x + bb.x, aa.y + bb.y);
        dstp[q + ((2 * p + 1) << st)] = make_float2(dx * cs - dy * sn, dx * sn + dy * cs);
        __syncthreads();
        float2* tmp = src; src = dstp; dstp = tmp;
        ncur >>= 1;
    }
    // src now holds Z[k] (natural order, 256 complex)
    if (t == 0) {
        float2 Z = src[128];
        atomicAdd(&sband[d_band[128]], Z.x * Z.x + Z.y * Z.y);
    } else {
        float2 Zk = src[t], Zn = src[256 - t];
        float Ex = 0.5f * (Zk.x + Zn.x), Ey = 0.5f * (Zk.y - Zn.y);
        float Dx = Zk.x - Zn.x, Dy = Zk.y + Zn.y;
        float Ox = 0.5f * Dy, Oy = -0.5f * Dx;
        float sn, cs;
        sincospif(-(float)t / 256.0f, &sn, &cs);
        float wox = Ox * cs - Oy * sn;
        float woy = Ox * sn + Oy * cs;
        float p1 = (Ex + wox) * (Ex + wox) + (Ey + woy) * (Ey + woy);   // |X[t]|^2
        float p2 = (Ex - wox) * (Ex - wox) + (Ey - woy) * (Ey - woy);   // |X[256-t]|^2
        atomicAdd(&sband[d_band[t]], p1);
        atomicAdd(&sband[d_band[256 - t]], p2);
    }
    __syncthreads();
    if (t < NBANDS) g_bark[kind][b][f][t] = sband[t] * d_powcorr[t];
}

// ============================ perceptual model ===============================
__global__ void k_silent() {
    int gw = (blockIdx.x * blockDim.x + threadIdx.x) >> 5;
    int lane = threadIdx.x & 31;
    if (gw >= NBATCH * NFRAMES) return;
    int b = gw / NFRAMES, f = gw % NFRAMES;
    float s = 0.f;
    for (int n = lane; n < NBANDS; n += 32) {
        if (n >= 1) {
            float v = g_bark[0][b][f][n];
            if (v > d_thresh[n] * 100.f) s += v;
        }
    }
    s = wredsum(s);
    if (lane == 0) {
        int sil = (s < 1e7f) ? 1 : 0;
        g_silent[b][f] = sil;
        if (!sil) atomicAdd(&g_cnt[b], 1);
    }
}

__global__ void k_timeavg() {
    int gw = (blockIdx.x * blockDim.x + threadIdx.x) >> 5;
    int lane = threadIdx.x & 31;
    if (gw >= NBATCH * NBANDS) return;
    int b = gw / NBANDS, n = gw % NBANDS;
    float th100 = d_thresh[n] * 100.f;
    float sd = 0.f, sr = 0.f;
    for (int f = lane; f < NFRAMES; f += 32) {
        if (!g_silent[b][f]) {
            float dv = g_bark[1][b][f][n];
            if (dv > th100) sd += dv;
            float rv = g_bark[0][b][f][n];
            if (rv > th100) sr += rv;
        }
    }
    sd = wredsum(sd);
    sr = wredsum(sr);
    if (lane == 0) {
        float cnt = (float)max(g_cnt[b], 1);
        float md = sd / cnt, mr = sr / cnt;
        float bpr = (md + 1000.f) / (mr + 1000.f);
        bpr = fminf(fmaxf(bpr, 0.01f), 100.f);
        g_bpr[b][n] = bpr;
    }
}

__global__ void k_fpr() {
    int gw = (blockIdx.x * blockDim.x + threadIdx.x) >> 5;
    int lane = threadIdx.x & 31;
    if (gw >= NBATCH * NFRAMES) return;
    int b = gw / NFRAMES, f = gw % NFRAMES;
    float taeq = 0.f, tad = 0.f;
    for (int n = lane; n < NBANDS; n += 32) {
        if (n >= 1) {
            float th = d_thresh[n];
            float eqr = g_bpr[b][n] * g_bark[0][b][f][n];
            if (eqr > th) taeq += eqr;
            float dv = g_bark[1][b][f][n];
            if (dv > th) tad += dv;
        }
    }
    taeq = wredsum(taeq);
    tad = wredsum(tad);
    if (lane == 0) {
        g_taeq[b][f] = taeq;
        g_fpr0[b][f] = (taeq + 5000.f) / (tad + 5000.f);
    }
}

__device__ __forceinline__ float loudf(float x, float th, float g) {
    if (x > th)
        return 1.866055e-1f * g * (powf(0.5f + 0.5f * x / th, 0.23f) - 1.f);
    return 0.f;
}

__global__ void k_dist() {
    int gw = (blockIdx.x * blockDim.x + threadIdx.x) >> 5;
    int lane = threadIdx.x & 31;
    if (gw >= NBATCH * NFRAMES) return;
    int b = gw / NFRAMES, f = gw % NFRAMES;
    float fp = g_fpr0[b][f];
    if (f > 0) fp = 0.8f * fp + 0.2f * g_fpr0[b][f - 1];
    fp = fminf(fmaxf(fp, 0.0003f), 5.0f);
    float w0 = d_w0, wsum = d_wsum;
    float acc2 = 0.f, acc1 = 0.f;
    for (int n = lane; n < NBANDS; n += 32) {
        float th = d_thresh[n], g = d_g023[n];
        float eqd = fp * g_bark[1][b][f][n];
        float eqr = g_bpr[b][n] * g_bark[0][b][f][n];
        float dl = loudf(eqd, th, g);
        float rl = loudf(eqr, th, g);
        float di = dl - rl;
        float dz = 0.25f * fminf(dl, rl);
        float ad = fmaxf(fabsf(di) - dz, 0.f);
        float t2 = ad * w0;
        acc2 += t2 * t2;
        float as = powf((eqd + 50.f) / (eqr + 50.f), 1.2f);
        as = (as < 3.f) ? 0.f : fminf(as, 12.f);
        acc1 += ad * as * w0;
    }
    acc2 = wredsum(acc2);
    acc1 = wredsum(acc1);
    if (lane == 0) {
        float symm = fmaxf(sqrtf(acc2 / wsum) * wsum, 1e-20f);
        float asym = fmaxf(acc1, 1e-20f);
        float h = powf((g_taeq[b][f] + 1e5f) * 1e-7f, 0.04f);
        g_symm[b][f] = fminf(symm / h, 45.f);
        g_asym[b][f] = fminf(asym / h, 45.f);
    }
}

__global__ void k_psqm(float* __restrict__ out) {
    int b = blockIdx.x, t = threadIdx.x;   // 64 threads
    float accS = 0.f, accA = 0.f;
    if (t < 61) {
        int base = t * 10;
        float m6s = 0.f, m6a = 0.f;
        #pragma unroll
        for (int i = 0; i < 20; i++) {
            float xs = g_symm[b][base + i];
            float x2 = xs * xs;
            m6s += x2 * x2 * x2;
            float xa = g_asym[b][base + i];
            float y2 = xa * xa;
            m6a += y2 * y2 * y2;
        }
        accS = cbrtf(m6s * (1.f / 20.f));   // (mean x^6)^{1/3} = p^2
        accA = cbrtf(m6a * (1.f / 20.f));
    }
    accS = wredsum(accS);
    accA = wredsum(accA);
    __shared__ float sS[2], sA[2];
    if ((t & 31) == 0) { sS[t >> 5] = accS; sA[t >> 5] = accA; }
    __syncthreads();
    if (t == 0) {
        float ds = sqrtf((sS[0] + sS[1]) / 61.f);
        float da = sqrtf((sA[0] + sA[1]) / 61.f);
        float mos = 4.5f - 0.1f * ds - 0.0309f * da;
        mos = 0.999f + 4.f / (1.f + expf(-1.3669f * mos + 3.8224f));
        out[b] = 0.5f * (4.5f - mos);
    }
}

// ============================ launch =========================================
extern "C" void kernel_launch(void* const* d_in, const int* in_sizes, int n_in,
                              void* d_out, int out_size) {
    const float* deg = (const float*)d_in[0];
    const float* ref = (const float*)d_in[1];
    float* out = (float*)d_out;

    k_init<<<1, 512>>>();
    k_zero<<<1, 64>>>();

    {   // IIR: 128 signals * 50 chunks = 6400 warps
        int warps = 2 * NBATCH * NCH;
        k_iir<<<warps * 32 / 256, 256>>>(deg, ref);
    }
    {
        dim3 gs(NFRAMES, NBATCH, 2);
        k_spec<<<gs, 128>>>();
    }
    k_silent<<<(NBATCH * NFRAMES) / 8, 256>>>();
    k_timeavg<<<(NBATCH * NBANDS) / 8, 256>>>();
    k_fpr<<<(NBATCH * NFRAMES) / 8, 256>>>();
    k_dist<<<(NBATCH * NFRAMES) / 8, 256>>>();
    k_psqm<<<NBATCH, 64>>>(out);
}

// round 3
// speedup vs baseline: 1.1018x; 1.1018x over previous
#include <cuda_runtime.h>
#include <math.h>

#define TLEN    160000
#define NBATCH  64
#define NFRAMES 624
#define NBANDS  49
#define CHUNK   3200
#define NCH     (TLEN/CHUNK)   // 50
#define FPW     4              // frames per warp in k_spec
#define FULLM   0xffffffffu

// ---------------- persistent device buffers ----------------------------------
__device__ float g_filt[2][NBATCH][TLEN];           // 0 = ref (from deg_in), 1 = deg (from ref_in)
__device__ float g_bark[2][NBATCH][NFRAMES][NBANDS];
__device__ int   g_silent[NBATCH][NFRAMES];
__device__ int   g_cnt[NBATCH];
__device__ float g_bpr[NBATCH][NBANDS];
__device__ float g_symm[NBATCH][NFRAMES];
__device__ float g_asym[NBATCH][NFRAMES];

// ---------------- tables ------------------------------------------------------
__device__ float d_hw[1024][2];    // A^d * c
__device__ float d_g64[64][2];     // A^{-1-i} * c
__device__ float d_r064[64][2];    // row 0 of A^m
__device__ float d_A64[4];         // A^64
__device__ int   d_band[256];
__device__ int   d_bs[50];         // band start bins (contiguous ranges)
__device__ float d_powcorr[NBANDS];
__device__ float d_thresh[NBANDS];
__device__ float d_g023[NBANDS];
__device__ float d_hann[512];
__device__ float d_w0, d_wsum;

__device__ __forceinline__ float wredsum(float v) {
    #pragma unroll
    for (int o = 16; o; o >>= 1) v += __shfl_xor_sync(FULLM, v, o);
    return v;
}

// ============================ table init =====================================
__device__ double u_closed(double d, double r, double th, double sinv) {
    return pow(r, d - 1.0) * sin(d * th) * sinv;
}

__global__ void k_init() {
    int t = threadIdx.x;           // 1024 threads
    __shared__ int s_cnt[NBANDS];
    if (t < NBANDS) s_cnt[t] = 0;
    __syncthreads();

    const double maxbark = 7.0 * asinh(8000.0 / 650.0);
    const double step = maxbark / 49.0;

    if (t < 256) {
        double f = (t + 0.5) * (16000.0 / 512.0);
        double bark = 7.0 * asinh(f / 650.0);
        int idx = 0;
        for (int j = 0; j <= 49; j++) {
            double e = (j == 49) ? maxbark : step * j;
            if (e <= bark) idx = j + 1;
        }
        int band = min(max(idx - 1, 0), 48);
        d_band[t] = band;
        atomicAdd(&s_cnt[band], 1);
    }
    if (t < 512)
        d_hann[t] = (float)(0.5 - 0.5 * cos(2.0 * 3.141592653589793 * t / 512.0));
    if (t < NBATCH) g_cnt[t] = 0;
    __syncthreads();

    if (t < NBANDS) {
        double cnt = s_cnt[t] > 1 ? (double)s_cnt[t] : 1.0;
        d_powcorr[t] = (float)(6.910853e-6 * 100.0 / cnt);
        double e0 = step * t;
        double e1 = (t == 48) ? maxbark : step * (t + 1);
        double fc = 650.0 * sinh(0.5 * (e0 + e1) / 7.0);
        if (fc < 20.0) fc = 20.0;
        fc /= 1000.0;
        double ath = 3.64 * pow(fc, -0.8) - 6.5 * exp(-0.6 * (fc - 3.3) * (fc - 3.3)) + 1e-3 * pow(fc, 4.0);
        double thv = pow(10.0, ath / 10.0);
        d_thresh[t] = (float)thv;
        d_g023[t] = (float)pow(thv / 0.5, 0.23);
    }

    // closed-form filter tables: A = [[P,1],[-Q,0]], A^d = u_d A - Q u_{d-1} I
    const double P = 1.9444777, Q = 0.94597794;
    const double B0 = 2.740826, B1 = -5.4816519, B2 = 2.740826;
    const double c0 = B1 + P * B0;
    const double c1 = B2 - Q * B0;
    const double r = sqrt(Q);
    const double s = sqrt(4.0 * Q - P * P);
    const double theta = atan2(s, P);
    const double sinv = 1.0 / sin(theta);

    {
        double u  = u_closed((double)t, r, theta, sinv);
        double um = u_closed((double)t - 1.0, r, theta, sinv);
        d_hw[t][0] = (float)(u * (P * c0 + c1) - Q * um * c0);
        d_hw[t][1] = (float)(-Q * u * c0 - Q * um * c1);
    }
    if (t < 64) {
        double d = -1.0 - (double)t;
        double u  = u_closed(d, r, theta, sinv);
        double um = u_closed(d - 1.0, r, theta, sinv);
        d_g64[t][0] = (float)(u * (P * c0 + c1) - Q * um * c0);
        d_g64[t][1] = (float)(-Q * u * c0 - Q * um * c1);
        double m = (double)t;
        double uM  = u_closed(m, r, theta, sinv);
        double uMm = u_closed(m - 1.0, r, theta, sinv);
        d_r064[t][0] = (float)(uM * P - Q * uMm);
        d_r064[t][1] = (float)uM;
    }
    if (t == 0) {
        double u64  = u_closed(64.0, r, theta, sinv);
        double u63  = u_closed(63.0, r, theta, sinv);
        d_A64[0] = (float)(u64 * P - Q * u63);
        d_A64[1] = (float)u64;
        d_A64[2] = (float)(-Q * u64);
        d_A64[3] = (float)(-Q * u63);

        float w0f = (float)step;
        float ws = 0.f;
        for (int i = 0; i < 49; i++) ws += w0f;
        d_w0 = w0f; d_wsum = ws;

        // band start table (bands are contiguous bin ranges)
        d_bs[0] = 0;
        for (int k = 1; k < 256; k++)
            if (d_band[k] != d_band[k - 1])
                for (int jj = d_band[k - 1] + 1; jj <= d_band[k]; jj++) d_bs[jj] = k;
        for (int jj = d_band[255] + 1; jj <= 49; jj++) d_bs[jj] = 256;
    }
}

// ============================ IIR (warp-parallel affine scan) ================
__global__ void k_iir(const float* __restrict__ deg_in, const float* __restrict__ ref_in) {
    int gw = (blockIdx.x * blockDim.x + threadIdx.x) >> 5;
    int lane = threadIdx.x & 31;
    int sig = gw / NCH;
    int ch = gw % NCH;
    if (sig >= 2 * NBATCH) return;
    int kind = sig & 1;
    int b = sig >> 1;
    const float* src = (kind == 0) ? deg_in + (size_t)b * TLEN : ref_in + (size_t)b * TLEN;
    const float scale = (kind == 0) ? 32320.01953125f : 23455.2265625f;
    float* dst = &g_filt[kind][b][0];
    const int t0 = ch * CHUNK;

    auto ld = [&](int t) -> float {
        float v = src[t] * scale;
        if (t < 15)               v *= (float)(t + 1) * 0.0625f;
        else if (t >= TLEN - 15)  v *= (float)(TLEN - t) * 0.0625f;
        return v;
    };

    float c0 = 0.f, c1 = 0.f;
    if (t0 > 0) {
        float a0 = 0.f, a1 = 0.f;
        #pragma unroll
        for (int it = 0; it < 32; it++) {
            int d = it * 32 + lane;
            float xv = ld(t0 - 1 - d);
            a0 += d_hw[d][0] * xv;
            a1 += d_hw[d][1] * xv;
        }
        c0 = wredsum(a0);
        c1 = wredsum(a1);
    }

    const float B0 = 2.740826f;
    const float A00 = d_A64[0], A01 = d_A64[1], A10 = d_A64[2], A11 = d_A64[3];
    const int i0 = 2 * lane, i1 = 2 * lane + 1;
    const float g00 = d_g64[i0][0], g01 = d_g64[i0][1];
    const float g10 = d_g64[i1][0], g11 = d_g64[i1][1];
    const float r00 = d_r064[i0][0], r01 = d_r064[i0][1];
    const float r10 = d_r064[i1][0], r11 = d_r064[i1][1];

    for (int blk = 0; blk < CHUNK / 64; blk++) {
        int base = t0 + blk * 64;
        int ta = base + i0;
        float x0 = ld(ta), x1 = ld(ta + 1);
        float u0 = g00 * x0 + g10 * x1;
        float u1 = g01 * x0 + g11 * x1;
        float p0 = u0, p1 = u1;
        #pragma unroll
        for (int d = 1; d < 32; d <<= 1) {
            float v0 = __shfl_up_sync(FULLM, p0, d);
            float v1 = __shfl_up_sync(FULLM, p1, d);
            if (lane >= d) { p0 += v0; p1 += v1; }
        }
        float tot0 = __shfl_sync(FULLM, p0, 31);
        float tot1 = __shfl_sync(FULLM, p1, 31);
        float e0 = p0 - u0, e1 = p1 - u1;
        float P0 = c0 + e0, P1 = c1 + e1;
        float y0 = B0 * x0 + (r00 * P0 + r01 * P1);
        float Q0 = P0 + g00 * x0, Q1 = P1 + g01 * x0;
        float y1 = B0 * x1 + (r10 * Q0 + r11 * Q1);
        *reinterpret_cast<float2*>(dst + ta) = make_float2(y0, y1);
        float n0 = c0 + tot0, n1 = c1 + tot1;
        c0 = A00 * n0 + A01 * n1;
        c1 = A10 * n0 + A11 * n1;
    }
}

// ============================ spectrogram + bark (warp FFT) ==================
// 256-pt complex FFT of packed real data, per warp: 256 = 8(reg) x 32(lane).
// Cross-lane 32-pt DIF via shfl_xor, in-register 8-pt DIF, lane-only twiddles.
__global__ void __launch_bounds__(256) k_spec() {
    const int lane = threadIdx.x & 31;
    const int wrp = threadIdx.x >> 5;
    const int task = blockIdx.x * 8 + wrp;       // 2*64*156 = 19968 tasks
    const int FG = NFRAMES / FPW;                // 156
    int tmp = task;
    const int fg = tmp % FG; tmp /= FG;
    const int b = tmp % NBATCH; tmp /= NBATCH;
    const int kind = tmp;

    __shared__ float sm[8][560];
    float* S = sm[wrp];

    const int k2 = __brev(lane) >> 27;           // bitrev5(lane)
    // cross-lane stage twiddles: stage s, span d=16>>s, W_{2d}^{lane & (d-1)}
    float twc[5], tws[5];
    #pragma unroll
    for (int s = 0; s < 5; s++) {
        int d = 16 >> s;
        sincospif(-(float)(lane & (d - 1)) / (float)d, &tws[s], &twc[s]);
    }
    float wc, ws;  sincospif(-(float)k2 / 128.0f, &ws, &wc);   // W256^{k2}
    float uc, us;  sincospif(-(float)k2 / 256.0f, &us, &uc);   // e^{-i pi k2/256}

    const int   BRT3[8] = {0, 4, 2, 6, 1, 5, 3, 7};
    const float C8[8]  = {1.f, 0.92387953f, 0.70710678f, 0.38268343f, 0.f, -0.38268343f, -0.70710678f, -0.92387953f};
    const float S8n[8] = {0.f, -0.38268343f, -0.70710678f, -0.92387953f, -1.f, -0.92387953f, -0.70710678f, -0.38268343f};
    const float R2 = 0.70710678f;

    const float* sig = &g_filt[kind][b][0];

    for (int fi = 0; fi < FPW; fi++) {
        const int f = fg * FPW + fi;
        const int base = f * 256;

        // ---- stage in (coalesced gmem -> padded shared) ----
        #pragma unroll
        for (int t = 0; t < 16; t++) {
            int n = lane + 32 * t;
            int sidx = base + n + kind;            // deg shifted by 1
            if (kind) sidx = min(sidx, TLEN - 1);
            float v = sig[sidx] * d_hann[n];
            S[n + (n >> 4)] = v;
        }
        __syncwarp();

        // ---- gather: lane holds z[8*lane + j] = x[16l+2j] + i x[16l+2j+1] ----
        float2 v[8];
        #pragma unroll
        for (int j = 0; j < 8; j++) {
            int a = 17 * lane + 2 * j;
            v[j].x = S[a]; v[j].y = S[a + 1];
        }
        __syncwarp();   // all gathers done before S reused for Z

        // ---- cross-lane 32-pt DIF (per slot) ----
        #pragma unroll
        for (int s = 0; s < 5; s++) {
            int d = 16 >> s;
            bool up = (lane & d) != 0;
            float tc = twc[s], ts_ = tws[s];
            #pragma unroll
            for (int j = 0; j < 8; j++) {
                float ox = __shfl_xor_sync(FULLM, v[j].x, d);
                float oy = __shfl_xor_sync(FULLM, v[j].y, d);
                if (up) {
                    float rx = ox - v[j].x, ry = oy - v[j].y;
                    v[j].x = rx * tc - ry * ts_;
                    v[j].y = rx * ts_ + ry * tc;
                } else { v[j].x += ox; v[j].y += oy; }
            }
        }

        // ---- twiddle W256^{n1*k2}, cumulative ----
        {
            float cc = wc, cs_ = ws;
            #pragma unroll
            for (int j = 1; j < 8; j++) {
                float nx = v[j].x * cc - v[j].y * cs_;
                float ny = v[j].x * cs_ + v[j].y * cc;
                v[j].x = nx; v[j].y = ny;
                if (j < 7) { float t0 = cc * wc - cs_ * ws; cs_ = cc * ws + cs_ * wc; cc = t0; }
            }
        }

        // ---- in-register 8-pt DIF over slots ----
        {
            // stage 1 span 4
            float tx, ty;
            tx = v[0].x - v[4].x; ty = v[0].y - v[4].y; v[0].x += v[4].x; v[0].y += v[4].y; v[4].x = tx; v[4].y = ty;
            tx = v[1].x - v[5].x; ty = v[1].y - v[5].y; v[1].x += v[5].x; v[1].y += v[5].y;
            v[5].x = R2 * (tx + ty); v[5].y = R2 * (ty - tx);
            tx = v[2].x - v[6].x; ty = v[2].y - v[6].y; v[2].x += v[6].x; v[2].y += v[6].y;
            v[6].x = ty; v[6].y = -tx;
            tx = v[3].x - v[7].x; ty = v[3].y - v[7].y; v[3].x += v[7].x; v[3].y += v[7].y;
            v[7].x = R2 * (ty - tx); v[7].y = -R2 * (tx + ty);
            // stage 2 span 2
            #pragma unroll
            for (int g = 0; g < 8; g += 4) {
                tx = v[g].x - v[g+2].x; ty = v[g].y - v[g+2].y; v[g].x += v[g+2].x; v[g].y += v[g+2].y; v[g+2].x = tx; v[g+2].y = ty;
                tx = v[g+1].x - v[g+3].x; ty = v[g+1].y - v[g+3].y; v[g+1].x += v[g+3].x; v[g+1].y += v[g+3].y;
                v[g+3].x = ty; v[g+3].y = -tx;   // * (-i)
            }
            // stage 3 span 1
            #pragma unroll
            for (int g = 0; g < 8; g += 2) {
                tx = v[g].x - v[g+1].x; ty = v[g].y - v[g+1].y; v[g].x += v[g+1].x; v[g].y += v[g+1].y; v[g+1].x = tx; v[g+1].y = ty;
            }
        }
        // slot j holds Z[32*BRT3[j] + k2]

        // ---- write Z to shared (conflict-free) ----
        #pragma unroll
        for (int j = 0; j < 8; j++) {
            int kk = 32 * BRT3[j] + k2;
            S[kk] = v[j].x; S[272 + kk] = v[j].y;
        }
        __syncwarp();

        // ---- unpack real FFT + power ----
        float p[8];
        #pragma unroll
        for (int j = 0; j < 8; j++) {
            int k1 = BRT3[j];
            int kk = 32 * k1 + k2;
            int kn = (256 - kk) & 255;
            float znr = S[kn], zni = S[272 + kn];
            float Ex = 0.5f * (v[j].x + znr), Ey = 0.5f * (v[j].y - zni);
            float Ox = 0.5f * (v[j].y + zni), Oy = -0.5f * (v[j].x - znr);
            float tc = uc * C8[k1] - us * S8n[k1];
            float ts_ = uc * S8n[k1] + us * C8[k1];
            float wox = Ox * tc - Oy * ts_;
            float woy = Ox * ts_ + Oy * tc;
            float Xr = Ex + wox, Xi = Ey + woy;
            float pw = Xr * Xr + Xi * Xi;
            p[j] = (kk == 0) ? 0.f : pw;          // bin 0 zeroed
        }
        __syncwarp();   // Z reads done before S reused for pw
        #pragma unroll
        for (int j = 0; j < 8; j++) S[32 * BRT3[j] + k2] = p[j];
        __syncwarp();

        // ---- contiguous band sums (no atomics) ----
        float acc0 = 0.f, acc1 = 0.f;
        {
            int s0 = d_bs[lane], e0 = d_bs[lane + 1];
            for (int i = s0; i < e0; i++) acc0 += S[i];
            if (lane < 17) {
                int s1 = d_bs[32 + lane], e1 = d_bs[33 + lane];
                for (int i = s1; i < e1; i++) acc1 += S[i];
            }
        }
        float v0 = acc0 * d_powcorr[lane];
        g_bark[kind][b][f][lane] = v0;
        float v1 = 0.f;
        if (lane < 17) {
            v1 = acc1 * d_powcorr[32 + lane];
            g_bark[kind][b][f][32 + lane] = v1;
        }

        // ---- silent detection fused (ref path only) ----
        if (kind == 0) {
            float sa = (lane >= 1 && v0 > d_thresh[lane] * 100.f) ? v0 : 0.f;
            if (lane < 17 && v1 > d_thresh[32 + lane] * 100.f) sa += v1;
            sa = wredsum(sa);
            if (lane == 0) {
                int sil = sa < 1e7f;
                g_silent[b][f] = sil;
                if (!sil) atomicAdd(&g_cnt[b], 1);
            }
        }
        __syncwarp();
    }
}

// ============================ time-avg + bpr (block per batch) ===============
__global__ void k_timeavg() {
    int b = blockIdx.x, t = threadIdx.x;        // 256 threads
    __shared__ float accd[NBANDS], accr[NBANDS];
    if (t < NBANDS) { accd[t] = 0.f; accr[t] = 0.f; }
    __syncthreads();
    for (int e = t; e < NFRAMES * NBANDS; e += 256) {
        int f = e / NBANDS, n = e % NBANDS;
        if (!g_silent[b][f]) {
            float th100 = d_thresh[n] * 100.f;
            float dv = g_bark[1][b][f][n];
            if (dv > th100) atomicAdd(&accd[n], dv);
            float rv = g_bark[0][b][f][n];
            if (rv > th100) atomicAdd(&accr[n], rv);
        }
    }
    __syncthreads();
    if (t < NBANDS) {
        float cnt = (float)max(g_cnt[b], 1);
        float md = accd[t] / cnt, mr = accr[t] / cnt;
        float bpr = (md + 1000.f) / (mr + 1000.f);
        g_bpr[b][t] = fminf(fmaxf(bpr, 0.01f), 100.f);
    }
}

// ============================ dist (fpr fused) ===============================
__device__ __forceinline__ float loudf(float x, float th, float g) {
    if (x > th)
        return 1.866055e-1f * g * (powf(0.5f + 0.5f * x / th, 0.23f) - 1.f);
    return 0.f;
}

__global__ void k_dist() {
    int gw = (blockIdx.x * blockDim.x + threadIdx.x) >> 5;
    int lane = threadIdx.x & 31;
    if (gw >= NBATCH * NFRAMES) return;
    int b = gw / NFRAMES, f = gw % NFRAMES;
    bool has1 = lane < 17;
    int n0 = lane, n1 = lane + 32;

    float th0 = d_thresh[n0], th1 = has1 ? d_thresh[n1] : 1.f;
    float bpr0 = g_bpr[b][n0], bpr1 = has1 ? g_bpr[b][n1] : 0.f;
    float r0 = g_bark[0][b][f][n0], d0 = g_bark[1][b][f][n0];
    float r1 = has1 ? g_bark[0][b][f][n1] : 0.f;
    float d1 = has1 ? g_bark[1][b][f][n1] : 0.f;
    float eqr0 = bpr0 * r0, eqr1 = bpr1 * r1;

    float taeq = ((n0 >= 1 && eqr0 > th0) ? eqr0 : 0.f) + ((has1 && eqr1 > th1) ? eqr1 : 0.f);
    float tad  = ((n0 >= 1 && d0  > th0) ? d0  : 0.f) + ((has1 && d1  > th1) ? d1  : 0.f);
    taeq = wredsum(taeq);
    tad  = wredsum(tad);
    float fp = (taeq + 5000.f) / (tad + 5000.f);

    if (f > 0) {
        float rp0 = g_bark[0][b][f-1][n0], dp0 = g_bark[1][b][f-1][n0];
        float rp1 = has1 ? g_bark[0][b][f-1][n1] : 0.f;
        float dp1 = has1 ? g_bark[1][b][f-1][n1] : 0.f;
        float ep0 = bpr0 * rp0, ep1 = bpr1 * rp1;
        float taeqP = ((n0 >= 1 && ep0 > th0) ? ep0 : 0.f) + ((has1 && ep1 > th1) ? ep1 : 0.f);
        float tadP  = ((n0 >= 1 && dp0 > th0) ? dp0 : 0.f) + ((has1 && dp1 > th1) ? dp1 : 0.f);
        taeqP = wredsum(taeqP);
        tadP  = wredsum(tadP);
        float fpP = (taeqP + 5000.f) / (tadP + 5000.f);
        fp = 0.8f * fp + 0.2f * fpP;
    }
    fp = fminf(fmaxf(fp, 0.0003f), 5.0f);

    float w0 = d_w0, wsum = d_wsum;
    float acc2 = 0.f, acc1 = 0.f;
    {
        float g0 = d_g023[n0];
        float eqd0 = fp * d0;
        float dl = loudf(eqd0, th0, g0);
        float rl = loudf(eqr0, th0, g0);
        float di = dl - rl;
        float dz = 0.25f * fminf(dl, rl);
        float ad = fmaxf(fabsf(di) - dz, 0.f);
        float t2 = ad * w0;
        acc2 += t2 * t2;
        float as = powf((eqd0 + 50.f) / (eqr0 + 50.f), 1.2f);
        as = (as < 3.f) ? 0.f : fminf(as, 12.f);
        acc1 += ad * as * w0;
    }
    if (has1) {
        float g1 = d_g023[n1];
        float eqd1 = fp * d1;
        float dl = loudf(eqd1, th1, g1);
        float rl = loudf(eqr1, th1, g1);
        float di = dl - rl;
        float dz = 0.25f * fminf(dl, rl);
        float ad = fmaxf(fabsf(di) - dz, 0.f);
        float t2 = ad * w0;
        acc2 += t2 * t2;
        float as = powf((eqd1 + 50.f) / (eqr1 + 50.f), 1.2f);
        as = (as < 3.f) ? 0.f : fminf(as, 12.f);
        acc1 += ad * as * w0;
    }
    acc2 = wredsum(acc2);
    acc1 = wredsum(acc1);
    if (lane == 0) {
        float symm = fmaxf(sqrtf(acc2 / wsum) * wsum, 1e-20f);
        float asym = fmaxf(acc1, 1e-20f);
        float h = powf((taeq + 1e5f) * 1e-7f, 0.04f);
        g_symm[b][f] = fminf(symm / h, 45.f);
        g_asym[b][f] = fminf(asym / h, 45.f);
    }
}

// ============================ psqm + mos =====================================
__global__ void k_psqm(float* __restrict__ out) {
    int b = blockIdx.x, t = threadIdx.x;   // 64 threads
    float accS = 0.f, accA = 0.f;
    if (t < 61) {
        int base = t * 10;
        float m6s = 0.f, m6a = 0.f;
        #pragma unroll
        for (int i = 0; i < 20; i++) {
            float xs = g_symm[b][base + i];
            float x2 = xs * xs;
            m6s += x2 * x2 * x2;
            float xa = g_asym[b][base + i];
            float y2 = xa * xa;
            m6a += y2 * y2 * y2;
        }
        accS = cbrtf(m6s * (1.f / 20.f));
        accA = cbrtf(m6a * (1.f / 20.f));
    }
    accS = wredsum(accS);
    accA = wredsum(accA);
    __shared__ float sS[2], sA[2];
    if ((t & 31) == 0) { sS[t >> 5] = accS; sA[t >> 5] = accA; }
    __syncthreads();
    if (t == 0) {
        float ds = sqrtf((sS[0] + sS[1]) / 61.f);
        float da = sqrtf((sA[0] + sA[1]) / 61.f);
        float mos = 4.5f - 0.1f * ds - 0.0309f * da;
        mos = 0.999f + 4.f / (1.f + expf(-1.3669f * mos + 3.8224f));
        out[b] = 0.5f * (4.5f - mos);
    }
}

// ============================ launch =========================================
extern "C" void kernel_launch(void* const* d_in, const int* in_sizes, int n_in,
                              void* d_out, int out_size) {
    const float* deg = (const float*)d_in[0];
    const float* ref = (const float*)d_in[1];
    float* out = (float*)d_out;

    k_init<<<1, 1024>>>();

    {   // IIR: 128 signals * 50 chunks = 6400 warps
        int warps = 2 * NBATCH * NCH;
        k_iir<<<warps * 32 / 256, 256>>>(deg, ref);
    }
    {   // spec: 2*64*156 warp-tasks, 8 warps/block
        int tasks = 2 * NBATCH * (NFRAMES / FPW);
        k_spec<<<tasks / 8, 256>>>();
    }
    k_timeavg<<<NBATCH, 256>>>();
    k_dist<<<(NBATCH * NFRAMES) / 8, 256>>>();
    k_psqm<<<NBATCH, 64>>>(out);
}

// round 4
// speedup vs baseline: 1.4375x; 1.3047x over previous
#include <cuda_runtime.h>
#include <math.h>

#define TLEN    160000
#define NBATCH  64
#define NFRAMES 624
#define NBANDS  49
#define CHUNK   3200
#define NCH     (TLEN/CHUNK)   // 50
#define FPW     4              // frames per warp in k_spec
#define NSLAB   8              // frame slabs in k_tsum (624 = 8*78)
#define FSLAB   (NFRAMES/NSLAB)
#define FULLM   0xffffffffu

// ---------------- persistent device buffers ----------------------------------
__device__ float g_filt[2][NBATCH][TLEN];           // 0 = ref (from deg_in), 1 = deg (from ref_in)
__device__ float g_bark[2][NBATCH][NFRAMES][NBANDS];
__device__ int   g_silent[NBATCH][NFRAMES];
__device__ int   g_cnt[NBATCH];
__device__ float g_accd[NBATCH][NBANDS];
__device__ float g_accr[NBATCH][NBANDS];
__device__ float g_symm[NBATCH][NFRAMES];
__device__ float g_asym[NBATCH][NFRAMES];

// ---------------- tables ------------------------------------------------------
__device__ float d_hw[1024][2];    // A^d * c
__device__ float d_g64[64][2];     // A^{-1-i} * c
__device__ float d_r064[64][2];    // row 0 of A^m
__device__ float d_A64[4];         // A^64
__device__ int   d_band[256];
__device__ int   d_bs[50];         // band start bins (contiguous ranges)
__device__ float d_powcorr[NBANDS];
__device__ float d_thresh[NBANDS];
__device__ float d_g023[NBANDS];
__device__ float d_hann[512];
__device__ float d_w0, d_wsum;

__device__ __forceinline__ float wredsum(float v) {
    #pragma unroll
    for (int o = 16; o; o >>= 1) v += __shfl_xor_sync(FULLM, v, o);
    return v;
}

// ============================ table init =====================================
__device__ double u_closed(double d, double r, double th, double sinv) {
    return pow(r, d - 1.0) * sin(d * th) * sinv;
}

__global__ void k_init() {
    int t = threadIdx.x;           // 1024 threads
    __shared__ int s_cnt[NBANDS];
    if (t < NBANDS) s_cnt[t] = 0;
    __syncthreads();

    const double maxbark = 7.0 * asinh(8000.0 / 650.0);
    const double step = maxbark / 49.0;

    if (t < 256) {
        double f = (t + 0.5) * (16000.0 / 512.0);
        double bark = 7.0 * asinh(f / 650.0);
        int idx = 0;
        for (int j = 0; j <= 49; j++) {
            double e = (j == 49) ? maxbark : step * j;
            if (e <= bark) idx = j + 1;
        }
        int band = min(max(idx - 1, 0), 48);
        d_band[t] = band;
        atomicAdd(&s_cnt[band], 1);
    }
    if (t < 512)
        d_hann[t] = (float)(0.5 - 0.5 * cos(2.0 * 3.141592653589793 * t / 512.0));
    if (t < NBATCH) g_cnt[t] = 0;
    for (int i = t; i < NBATCH * NBANDS; i += 1024) {
        (&g_accd[0][0])[i] = 0.f;
        (&g_accr[0][0])[i] = 0.f;
    }
    __syncthreads();

    if (t < NBANDS) {
        double cnt = s_cnt[t] > 1 ? (double)s_cnt[t] : 1.0;
        d_powcorr[t] = (float)(6.910853e-6 * 100.0 / cnt);
        double e0 = step * t;
        double e1 = (t == 48) ? maxbark : step * (t + 1);
        double fc = 650.0 * sinh(0.5 * (e0 + e1) / 7.0);
        if (fc < 20.0) fc = 20.0;
        fc /= 1000.0;
        double ath = 3.64 * pow(fc, -0.8) - 6.5 * exp(-0.6 * (fc - 3.3) * (fc - 3.3)) + 1e-3 * pow(fc, 4.0);
        double thv = pow(10.0, ath / 10.0);
        d_thresh[t] = (float)thv;
        d_g023[t] = (float)pow(thv / 0.5, 0.23);
    }

    // closed-form filter tables: A = [[P,1],[-Q,0]], A^d = u_d A - Q u_{d-1} I
    const double P = 1.9444777, Q = 0.94597794;
    const double B0 = 2.740826, B1 = -5.4816519, B2 = 2.740826;
    const double c0 = B1 + P * B0;
    const double c1 = B2 - Q * B0;
    const double r = sqrt(Q);
    const double s = sqrt(4.0 * Q - P * P);
    const double theta = atan2(s, P);
    const double sinv = 1.0 / sin(theta);

    {
        double u  = u_closed((double)t, r, theta, sinv);
        double um = u_closed((double)t - 1.0, r, theta, sinv);
        d_hw[t][0] = (float)(u * (P * c0 + c1) - Q * um * c0);
        d_hw[t][1] = (float)(-Q * u * c0 - Q * um * c1);
    }
    if (t < 64) {
        double d = -1.0 - (double)t;
        double u  = u_closed(d, r, theta, sinv);
        double um = u_closed(d - 1.0, r, theta, sinv);
        d_g64[t][0] = (float)(u * (P * c0 + c1) - Q * um * c0);
        d_g64[t][1] = (float)(-Q * u * c0 - Q * um * c1);
        double m = (double)t;
        double uM  = u_closed(m, r, theta, sinv);
        double uMm = u_closed(m - 1.0, r, theta, sinv);
        d_r064[t][0] = (float)(uM * P - Q * uMm);
        d_r064[t][1] = (float)uM;
    }
    if (t == 0) {
        double u64  = u_closed(64.0, r, theta, sinv);
        double u63  = u_closed(63.0, r, theta, sinv);
        d_A64[0] = (float)(u64 * P - Q * u63);
        d_A64[1] = (float)u64;
        d_A64[2] = (float)(-Q * u64);
        d_A64[3] = (float)(-Q * u63);

        float w0f = (float)step;
        float ws = 0.f;
        for (int i = 0; i < 49; i++) ws += w0f;
        d_w0 = w0f; d_wsum = ws;

        // band start table (bands are contiguous bin ranges)
        d_bs[0] = 0;
        for (int k = 1; k < 256; k++)
            if (d_band[k] != d_band[k - 1])
                for (int jj = d_band[k - 1] + 1; jj <= d_band[k]; jj++) d_bs[jj] = k;
        for (int jj = d_band[255] + 1; jj <= 49; jj++) d_bs[jj] = 256;
    }
}

// ============================ IIR (warp-parallel affine scan) ================
__global__ void k_iir(const float* __restrict__ deg_in, const float* __restrict__ ref_in) {
    int gw = (blockIdx.x * blockDim.x + threadIdx.x) >> 5;
    int lane = threadIdx.x & 31;
    int sig = gw / NCH;
    int ch = gw % NCH;
    if (sig >= 2 * NBATCH) return;
    int kind = sig & 1;
    int b = sig >> 1;
    const float* src = (kind == 0) ? deg_in + (size_t)b * TLEN : ref_in + (size_t)b * TLEN;
    const float scale = (kind == 0) ? 32320.01953125f : 23455.2265625f;
    float* dst = &g_filt[kind][b][0];
    const int t0 = ch * CHUNK;

    auto ld = [&](int t) -> float {
        float v = src[t] * scale;
        if (t < 15)               v *= (float)(t + 1) * 0.0625f;
        else if (t >= TLEN - 15)  v *= (float)(TLEN - t) * 0.0625f;
        return v;
    };

    float c0 = 0.f, c1 = 0.f;
    if (t0 > 0) {
        float a0 = 0.f, a1 = 0.f;
        #pragma unroll
        for (int it = 0; it < 32; it++) {
            int d = it * 32 + lane;
            float xv = ld(t0 - 1 - d);
            a0 += d_hw[d][0] * xv;
            a1 += d_hw[d][1] * xv;
        }
        c0 = wredsum(a0);
        c1 = wredsum(a1);
    }

    const float B0 = 2.740826f;
    const float A00 = d_A64[0], A01 = d_A64[1], A10 = d_A64[2], A11 = d_A64[3];
    const int i0 = 2 * lane, i1 = 2 * lane + 1;
    const float g00 = d_g64[i0][0], g01 = d_g64[i0][1];
    const float g10 = d_g64[i1][0], g11 = d_g64[i1][1];
    const float r00 = d_r064[i0][0], r01 = d_r064[i0][1];
    const float r10 = d_r064[i1][0], r11 = d_r064[i1][1];

    for (int blk = 0; blk < CHUNK / 64; blk++) {
        int base = t0 + blk * 64;
        int ta = base + i0;
        float x0 = ld(ta), x1 = ld(ta + 1);
        float u0 = g00 * x0 + g10 * x1;
        float u1 = g01 * x0 + g11 * x1;
        float p0 = u0, p1 = u1;
        #pragma unroll
        for (int d = 1; d < 32; d <<= 1) {
            float v0 = __shfl_up_sync(FULLM, p0, d);
            float v1 = __shfl_up_sync(FULLM, p1, d);
            if (lane >= d) { p0 += v0; p1 += v1; }
        }
        float tot0 = __shfl_sync(FULLM, p0, 31);
        float tot1 = __shfl_sync(FULLM, p1, 31);
        float e0 = p0 - u0, e1 = p1 - u1;
        float P0 = c0 + e0, P1 = c1 + e1;
        float y0 = B0 * x0 + (r00 * P0 + r01 * P1);
        float Q0 = P0 + g00 * x0, Q1 = P1 + g01 * x0;
        float y1 = B0 * x1 + (r10 * Q0 + r11 * Q1);
        *reinterpret_cast<float2*>(dst + ta) = make_float2(y0, y1);
        float n0 = c0 + tot0, n1 = c1 + tot1;
        c0 = A00 * n0 + A01 * n1;
        c1 = A10 * n0 + A11 * n1;
    }
}

// ============================ spectrogram + bark (warp FFT) ==================
// 256-pt complex FFT of packed real data, per warp: 256 = 8(reg) x 32(lane).
// Cross-lane 32-pt DIF via shfl_xor, in-register 8-pt DIF, lane-only twiddles.
__global__ void __launch_bounds__(256) k_spec() {
    const int lane = threadIdx.x & 31;
    const int wrp = threadIdx.x >> 5;
    const int task = blockIdx.x * 8 + wrp;       // 2*64*156 = 19968 tasks
    const int FG = NFRAMES / FPW;                // 156
    int tmp = task;
    const int fg = tmp % FG; tmp /= FG;
    const int b = tmp % NBATCH; tmp /= NBATCH;
    const int kind = tmp;

    __shared__ float sm[8][560];
    float* S = sm[wrp];

    const int k2 = __brev(lane) >> 27;           // bitrev5(lane)
    // cross-lane stage twiddles: stage s, span d=16>>s, W_{2d}^{lane & (d-1)}
    float twc[5], tws[5];
    #pragma unroll
    for (int s = 0; s < 5; s++) {
        int d = 16 >> s;
        sincospif(-(float)(lane & (d - 1)) / (float)d, &tws[s], &twc[s]);
    }
    float wc, ws;  sincospif(-(float)k2 / 128.0f, &ws, &wc);   // W256^{k2}
    float uc, us;  sincospif(-(float)k2 / 256.0f, &us, &uc);   // e^{-i pi k2/256}

    const int   BRT3[8] = {0, 4, 2, 6, 1, 5, 3, 7};
    const float C8[8]  = {1.f, 0.92387953f, 0.70710678f, 0.38268343f, 0.f, -0.38268343f, -0.70710678f, -0.92387953f};
    const float S8n[8] = {0.f, -0.38268343f, -0.70710678f, -0.92387953f, -1.f, -0.92387953f, -0.70710678f, -0.38268343f};
    const float R2 = 0.70710678f;

    const float* sig = &g_filt[kind][b][0];

    for (int fi = 0; fi < FPW; fi++) {
        const int f = fg * FPW + fi;
        const int base = f * 256;

        // ---- stage in (coalesced gmem -> padded shared) ----
        #pragma unroll
        for (int t = 0; t < 16; t++) {
            int n = lane + 32 * t;
            int sidx = base + n + kind;            // deg shifted by 1
            if (kind) sidx = min(sidx, TLEN - 1);
            float v = sig[sidx] * d_hann[n];
            S[n + (n >> 4)] = v;
        }
        __syncwarp();

        // ---- gather: lane holds z[8*lane + j] = x[16l+2j] + i x[16l+2j+1] ----
        float2 v[8];
        #pragma unroll
        for (int j = 0; j < 8; j++) {
            int a = 17 * lane + 2 * j;
            v[j].x = S[a]; v[j].y = S[a + 1];
        }
        __syncwarp();   // all gathers done before S reused for Z

        // ---- cross-lane 32-pt DIF (per slot) ----
        #pragma unroll
        for (int s = 0; s < 5; s++) {
            int d = 16 >> s;
            bool up = (lane & d) != 0;
            float tc = twc[s], ts_ = tws[s];
            #pragma unroll
            for (int j = 0; j < 8; j++) {
                float ox = __shfl_xor_sync(FULLM, v[j].x, d);
                float oy = __shfl_xor_sync(FULLM, v[j].y, d);
                if (up) {
                    float rx = ox - v[j].x, ry = oy - v[j].y;
                    v[j].x = rx * tc - ry * ts_;
                    v[j].y = rx * ts_ + ry * tc;
                } else { v[j].x += ox; v[j].y += oy; }
            }
        }

        // ---- twiddle W256^{n1*k2}, cumulative ----
        {
            float cc = wc, cs_ = ws;
            #pragma unroll
            for (int j = 1; j < 8; j++) {
                float nx = v[j].x * cc - v[j].y * cs_;
                float ny = v[j].x * cs_ + v[j].y * cc;
                v[j].x = nx; v[j].y = ny;
                if (j < 7) { float t0 = cc * wc - cs_ * ws; cs_ = cc * ws + cs_ * wc; cc = t0; }
            }
        }

        // ---- in-register 8-pt DIF over slots ----
        {
            // stage 1 span 4
            float tx, ty;
            tx = v[0].x - v[4].x; ty = v[0].y - v[4].y; v[0].x += v[4].x; v[0].y += v[4].y; v[4].x = tx; v[4].y = ty;
            tx = v[1].x - v[5].x; ty = v[1].y - v[5].y; v[1].x += v[5].x; v[1].y += v[5].y;
            v[5].x = R2 * (tx + ty); v[5].y = R2 * (ty - tx);
            tx = v[2].x - v[6].x; ty = v[2].y - v[6].y; v[2].x += v[6].x; v[2].y += v[6].y;
            v[6].x = ty; v[6].y = -tx;
            tx = v[3].x - v[7].x; ty = v[3].y - v[7].y; v[3].x += v[7].x; v[3].y += v[7].y;
            v[7].x = R2 * (ty - tx); v[7].y = -R2 * (tx + ty);
            // stage 2 span 2
            #pragma unroll
            for (int g = 0; g < 8; g += 4) {
                tx = v[g].x - v[g+2].x; ty = v[g].y - v[g+2].y; v[g].x += v[g+2].x; v[g].y += v[g+2].y; v[g+2].x = tx; v[g+2].y = ty;
                tx = v[g+1].x - v[g+3].x; ty = v[g+1].y - v[g+3].y; v[g+1].x += v[g+3].x; v[g+1].y += v[g+3].y;
                v[g+3].x = ty; v[g+3].y = -tx;   // * (-i)
            }
            // stage 3 span 1
            #pragma unroll
            for (int g = 0; g < 8; g += 2) {
                tx = v[g].x - v[g+1].x; ty = v[g].y - v[g+1].y; v[g].x += v[g+1].x; v[g].y += v[g+1].y; v[g+1].x = tx; v[g+1].y = ty;
            }
        }
        // slot j holds Z[32*BRT3[j] + k2]

        // ---- write Z to shared (conflict-free) ----
        #pragma unroll
        for (int j = 0; j < 8; j++) {
            int kk = 32 * BRT3[j] + k2;
            S[kk] = v[j].x; S[272 + kk] = v[j].y;
        }
        __syncwarp();

        // ---- unpack real FFT + power ----
        float p[8];
        #pragma unroll
        for (int j = 0; j < 8; j++) {
            int k1 = BRT3[j];
            int kk = 32 * k1 + k2;
            int kn = (256 - kk) & 255;
            float znr = S[kn], zni = S[272 + kn];
            float Ex = 0.5f * (v[j].x + znr), Ey = 0.5f * (v[j].y - zni);
            float Ox = 0.5f * (v[j].y + zni), Oy = -0.5f * (v[j].x - znr);
            float tc = uc * C8[k1] - us * S8n[k1];
            float ts_ = uc * S8n[k1] + us * C8[k1];
            float wox = Ox * tc - Oy * ts_;
            float woy = Ox * ts_ + Oy * tc;
            float Xr = Ex + wox, Xi = Ey + woy;
            float pw = Xr * Xr + Xi * Xi;
            p[j] = (kk == 0) ? 0.f : pw;          // bin 0 zeroed
        }
        __syncwarp();   // Z reads done before S reused for pw
        #pragma unroll
        for (int j = 0; j < 8; j++) S[32 * BRT3[j] + k2] = p[j];
        __syncwarp();

        // ---- contiguous band sums (no atomics) ----
        float acc0 = 0.f, acc1 = 0.f;
        {
            int s0 = d_bs[lane], e0 = d_bs[lane + 1];
            for (int i = s0; i < e0; i++) acc0 += S[i];
            if (lane < 17) {
                int s1 = d_bs[32 + lane], e1 = d_bs[33 + lane];
                for (int i = s1; i < e1; i++) acc1 += S[i];
            }
        }
        float v0 = acc0 * d_powcorr[lane];
        g_bark[kind][b][f][lane] = v0;
        float v1 = 0.f;
        if (lane < 17) {
            v1 = acc1 * d_powcorr[32 + lane];
            g_bark[kind][b][f][32 + lane] = v1;
        }

        // ---- silent detection fused (ref path only) ----
        if (kind == 0) {
            float sa = (lane >= 1 && v0 > d_thresh[lane] * 100.f) ? v0 : 0.f;
            if (lane < 17 && v1 > d_thresh[32 + lane] * 100.f) sa += v1;
            sa = wredsum(sa);
            if (lane == 0) {
                int sil = sa < 1e7f;
                g_silent[b][f] = sil;
                if (!sil) atomicAdd(&g_cnt[b], 1);
            }
        }
        __syncwarp();
    }
}

// ============================ time-avg partial sums ==========================
// grid (NBATCH, NSLAB); block 256 = 4 frame-phases x 64 band slots.
// Private register accumulation, 4-way shared reduce, global atomic combine.
__global__ void k_tsum() {
    int b = blockIdx.x, slab = blockIdx.y;
    int t = threadIdx.x;
    int n = t & 63, fi = t >> 6;
    bool act = n < NBANDS;
    float ad = 0.f, ar = 0.f;
    int f0 = slab * FSLAB;
    if (act) {
        float th100 = d_thresh[n] * 100.f;
        for (int f = f0 + fi; f < f0 + FSLAB; f += 4) {
            if (!g_silent[b][f]) {
                float dv = g_bark[1][b][f][n];
                if (dv > th100) ad += dv;
                float rv = g_bark[0][b][f][n];
                if (rv > th100) ar += rv;
            }
        }
    }
    __shared__ float sd[4][64], sr[4][64];
    sd[fi][n] = ad; sr[fi][n] = ar;
    __syncthreads();
    if (fi == 0 && act) {
        atomicAdd(&g_accd[b][n], sd[0][n] + sd[1][n] + sd[2][n] + sd[3][n]);
        atomicAdd(&g_accr[b][n], sr[0][n] + sr[1][n] + sr[2][n] + sr[3][n]);
    }
}

// ============================ dist (fpr + bpr fused) =========================
__device__ __forceinline__ float loudf(float x, float th, float g) {
    if (x > th)
        return 1.866055e-1f * g * (powf(0.5f + 0.5f * x / th, 0.23f) - 1.f);
    return 0.f;
}

__global__ void k_dist() {
    int gw = (blockIdx.x * blockDim.x + threadIdx.x) >> 5;
    int lane = threadIdx.x & 31;
    if (gw >= NBATCH * NFRAMES) return;
    int b = gw / NFRAMES, f = gw % NFRAMES;
    bool has1 = lane < 17;
    int n0 = lane, n1 = lane + 32;

    float cntInv = 1.f / (float)max(g_cnt[b], 1);
    float th0 = d_thresh[n0], th1 = has1 ? d_thresh[n1] : 1.f;
    float bpr0, bpr1 = 0.f;
    {
        float md = g_accd[b][n0] * cntInv, mr = g_accr[b][n0] * cntInv;
        bpr0 = fminf(fmaxf((md + 1000.f) / (mr + 1000.f), 0.01f), 100.f);
        if (has1) {
            float md1 = g_accd[b][n1] * cntInv, mr1 = g_accr[b][n1] * cntInv;
            bpr1 = fminf(fmaxf((md1 + 1000.f) / (mr1 + 1000.f), 0.01f), 100.f);
        }
    }
    float r0 = g_bark[0][b][f][n0], d0 = g_bark[1][b][f][n0];
    float r1 = has1 ? g_bark[0][b][f][n1] : 0.f;
    float d1 = has1 ? g_bark[1][b][f][n1] : 0.f;
    float eqr0 = bpr0 * r0, eqr1 = bpr1 * r1;

    float taeq = ((n0 >= 1 && eqr0 > th0) ? eqr0 : 0.f) + ((has1 && eqr1 > th1) ? eqr1 : 0.f);
    float tad  = ((n0 >= 1 && d0  > th0) ? d0  : 0.f) + ((has1 && d1  > th1) ? d1  : 0.f);
    taeq = wredsum(taeq);
    tad  = wredsum(tad);
    float fp = (taeq + 5000.f) / (tad + 5000.f);

    if (f > 0) {
        float rp0 = g_bark[0][b][f-1][n0], dp0 = g_bark[1][b][f-1][n0];
        float rp1 = has1 ? g_bark[0][b][f-1][n1] : 0.f;
        float dp1 = has1 ? g_bark[1][b][f-1][n1] : 0.f;
        float ep0 = bpr0 * rp0, ep1 = bpr1 * rp1;
        float taeqP = ((n0 >= 1 && ep0 > th0) ? ep0 : 0.f) + ((has1 && ep1 > th1) ? ep1 : 0.f);
        float tadP  = ((n0 >= 1 && dp0 > th0) ? dp0 : 0.f) + ((has1 && dp1 > th1) ? dp1 : 0.f);
        taeqP = wredsum(taeqP);
        tadP  = wredsum(tadP);
        float fpP = (taeqP + 5000.f) / (tadP + 5000.f);
        fp = 0.8f * fp + 0.2f * fpP;
    }
    fp = fminf(fmaxf(fp, 0.0003f), 5.0f);

    float w0 = d_w0, wsum = d_wsum;
    float acc2 = 0.f, acc1 = 0.f;
    {
        float g0 = d_g023[n0];
        float eqd0 = fp * d0;
        float dl = loudf(eqd0, th0, g0);
        float rl = loudf(eqr0, th0, g0);
        float di = dl - rl;
        float dz = 0.25f * fminf(dl, rl);
        float ad = fmaxf(fabsf(di) - dz, 0.f);
        float t2 = ad * w0;
        acc2 += t2 * t2;
        float as = powf((eqd0 + 50.f) / (eqr0 + 50.f), 1.2f);
        as = (as < 3.f) ? 0.f : fminf(as, 12.f);
        acc1 += ad * as * w0;
    }
    if (has1) {
        float g1 = d_g023[n1];
        float eqd1 = fp * d1;
        float dl = loudf(eqd1, th1, g1);
        float rl = loudf(eqr1, th1, g1);
        float di = dl - rl;
        float dz = 0.25f * fminf(dl, rl);
        float ad = fmaxf(fabsf(di) - dz, 0.f);
        float t2 = ad * w0;
        acc2 += t2 * t2;
        float as = powf((eqd1 + 50.f) / (eqr1 + 50.f), 1.2f);
        as = (as < 3.f) ? 0.f : fminf(as, 12.f);
        acc1 += ad * as * w0;
    }
    acc2 = wredsum(acc2);
    acc1 = wredsum(acc1);
    if (lane == 0) {
        float symm = fmaxf(sqrtf(acc2 / wsum) * wsum, 1e-20f);
        float asym = fmaxf(acc1, 1e-20f);
        float h = powf((taeq + 1e5f) * 1e-7f, 0.04f);
        g_symm[b][f] = fminf(symm / h, 45.f);
        g_asym[b][f] = fminf(asym / h, 45.f);
    }
}

// ============================ psqm + mos =====================================
__global__ void k_psqm(float* __restrict__ out) {
    int b = blockIdx.x, t = threadIdx.x;   // 64 threads
    float accS = 0.f, accA = 0.f;
    if (t < 61) {
        int base = t * 10;
        float m6s = 0.f, m6a = 0.f;
        #pragma unroll
        for (int i = 0; i < 20; i++) {
            float xs = g_symm[b][base + i];
            float x2 = xs * xs;
            m6s += x2 * x2 * x2;
            float xa = g_asym[b][base + i];
            float y2 = xa * xa;
            m6a += y2 * y2 * y2;
        }
        accS = cbrtf(m6s * (1.f / 20.f));
        accA = cbrtf(m6a * (1.f / 20.f));
    }
    accS = wredsum(accS);
    accA = wredsum(accA);
    __shared__ float sS[2], sA[2];
    if ((t & 31) == 0) { sS[t >> 5] = accS; sA[t >> 5] = accA; }
    __syncthreads();
    if (t == 0) {
        float ds = sqrtf((sS[0] + sS[1]) / 61.f);
        float da = sqrtf((sA[0] + sA[1]) / 61.f);
        float mos = 4.5f - 0.1f * ds - 0.0309f * da;
        mos = 0.999f + 4.f / (1.f + expf(-1.3669f * mos + 3.8224f));
        out[b] = 0.5f * (4.5f - mos);
    }
}

// ============================ launch =========================================
extern "C" void kernel_launch(void* const* d_in, const int* in_sizes, int n_in,
                              void* d_out, int out_size) {
    const float* deg = (const float*)d_in[0];
    const float* ref = (const float*)d_in[1];
    float* out = (float*)d_out;

    k_init<<<1, 1024>>>();

    {   // IIR: 128 signals * 50 chunks = 6400 warps
        int warps = 2 * NBATCH * NCH;
        k_iir<<<warps * 32 / 256, 256>>>(deg, ref);
    }
    {   // spec: 2*64*156 warp-tasks, 8 warps/block
        int tasks = 2 * NBATCH * (NFRAMES / FPW);
        k_spec<<<tasks / 8, 256>>>();
    }
    {
        dim3 gs(NBATCH, NSLAB);
        k_tsum<<<gs, 256>>>();
    }
    k_dist<<<(NBATCH * NFRAMES) / 8, 256>>>();
    k_psqm<<<NBATCH, 64>>>(out);
}

// round 5
// speedup vs baseline: 1.5588x; 1.0843x over previous
#include <cuda_runtime.h>
#include <math.h>

#define TLEN    160000
#define NBATCH  64
#define NFRAMES 624
#define NBANDS  49
#define CHUNK   3200
#define NCH     (TLEN/CHUNK)   // 50
#define FPW     4              // frames per warp in k_spec
#define DFR     4              // frames per warp in k_dist
#define NSLAB   8              // frame slabs in k_tsum (624 = 8*78)
#define FSLAB   (NFRAMES/NSLAB)
#define FULLM   0xffffffffu

// ---------------- persistent device buffers ----------------------------------
__device__ float g_filt[2][NBATCH][TLEN];           // 0 = ref; 1 = deg (stored pre-shifted by 1)
__device__ float g_bark[2][NBATCH][NFRAMES][NBANDS];
__device__ int   g_silent[NBATCH][NFRAMES];
__device__ int   g_cnt[NBATCH];
__device__ float g_accd[NBATCH][NBANDS];
__device__ float g_accr[NBATCH][NBANDS];
__device__ float g_symm[NBATCH][NFRAMES];
__device__ float g_asym[NBATCH][NFRAMES];

// ---------------- tables ------------------------------------------------------
__device__ float d_hw[1024][2];    // A^d * c
__device__ float d_g64[64][2];     // A^{-1-i} * c
__device__ float d_r064[64][2];    // row 0 of A^m
__device__ float d_A64[4];         // A^64
__device__ int   d_band[256];
__device__ int   d_bs[50];         // band start bins (contiguous ranges)
__device__ float d_powcorr[NBANDS];
__device__ float d_thresh[NBANDS];
__device__ float d_g023[NBANDS];
__device__ float d_hann[512];
__device__ float d_w0, d_wsum;

__device__ __forceinline__ float wredsum(float v) {
    #pragma unroll
    for (int o = 16; o; o >>= 1) v += __shfl_xor_sync(FULLM, v, o);
    return v;
}

// ============================ table init =====================================
__device__ double u_closed(double d, double r, double th, double sinv) {
    return pow(r, d - 1.0) * sin(d * th) * sinv;
}

__global__ void k_init() {
    int t = threadIdx.x;           // 1024 threads
    __shared__ int s_cnt[NBANDS];
    if (t < NBANDS) s_cnt[t] = 0;
    __syncthreads();

    const double maxbark = 7.0 * asinh(8000.0 / 650.0);
    const double step = maxbark / 49.0;

    if (t < 256) {
        double f = (t + 0.5) * (16000.0 / 512.0);
        double bark = 7.0 * asinh(f / 650.0);
        int idx = 0;
        for (int j = 0; j <= 49; j++) {
            double e = (j == 49) ? maxbark : step * j;
            if (e <= bark) idx = j + 1;
        }
        int band = min(max(idx - 1, 0), 48);
        d_band[t] = band;
        atomicAdd(&s_cnt[band], 1);
    }
    if (t < 512)
        d_hann[t] = (float)(0.5 - 0.5 * cos(2.0 * 3.141592653589793 * t / 512.0));
    if (t < NBATCH) g_cnt[t] = 0;
    for (int i = t; i < NBATCH * NBANDS; i += 1024) {
        (&g_accd[0][0])[i] = 0.f;
        (&g_accr[0][0])[i] = 0.f;
    }
    __syncthreads();

    if (t < NBANDS) {
        double cnt = s_cnt[t] > 1 ? (double)s_cnt[t] : 1.0;
        d_powcorr[t] = (float)(6.910853e-6 * 100.0 / cnt);
        double e0 = step * t;
        double e1 = (t == 48) ? maxbark : step * (t + 1);
        double fc = 650.0 * sinh(0.5 * (e0 + e1) / 7.0);
        if (fc < 20.0) fc = 20.0;
        fc /= 1000.0;
        double ath = 3.64 * pow(fc, -0.8) - 6.5 * exp(-0.6 * (fc - 3.3) * (fc - 3.3)) + 1e-3 * pow(fc, 4.0);
        double thv = pow(10.0, ath / 10.0);
        d_thresh[t] = (float)thv;
        d_g023[t] = (float)pow(thv / 0.5, 0.23);
    }

    // closed-form filter tables: A = [[P,1],[-Q,0]], A^d = u_d A - Q u_{d-1} I
    const double P = 1.9444777, Q = 0.94597794;
    const double B0 = 2.740826, B1 = -5.4816519, B2 = 2.740826;
    const double c0 = B1 + P * B0;
    const double c1 = B2 - Q * B0;
    const double r = sqrt(Q);
    const double s = sqrt(4.0 * Q - P * P);
    const double theta = atan2(s, P);
    const double sinv = 1.0 / sin(theta);

    {
        double u  = u_closed((double)t, r, theta, sinv);
        double um = u_closed((double)t - 1.0, r, theta, sinv);
        d_hw[t][0] = (float)(u * (P * c0 + c1) - Q * um * c0);
        d_hw[t][1] = (float)(-Q * u * c0 - Q * um * c1);
    }
    if (t < 64) {
        double d = -1.0 - (double)t;
        double u  = u_closed(d, r, theta, sinv);
        double um = u_closed(d - 1.0, r, theta, sinv);
        d_g64[t][0] = (float)(u * (P * c0 + c1) - Q * um * c0);
        d_g64[t][1] = (float)(-Q * u * c0 - Q * um * c1);
        double m = (double)t;
        double uM  = u_closed(m, r, theta, sinv);
        double uMm = u_closed(m - 1.0, r, theta, sinv);
        d_r064[t][0] = (float)(uM * P - Q * uMm);
        d_r064[t][1] = (float)uM;
    }
    if (t == 0) {
        double u64  = u_closed(64.0, r, theta, sinv);
        double u63  = u_closed(63.0, r, theta, sinv);
        d_A64[0] = (float)(u64 * P - Q * u63);
        d_A64[1] = (float)u64;
        d_A64[2] = (float)(-Q * u64);
        d_A64[3] = (float)(-Q * u63);

        float w0f = (float)step;
        float ws = 0.f;
        for (int i = 0; i < 49; i++) ws += w0f;
        d_w0 = w0f; d_wsum = ws;

        // band start table (bands are contiguous bin ranges)
        d_bs[0] = 0;
        for (int k = 1; k < 256; k++)
            if (d_band[k] != d_band[k - 1])
                for (int jj = d_band[k - 1] + 1; jj <= d_band[k]; jj++) d_bs[jj] = k;
        for (int jj = d_band[255] + 1; jj <= 49; jj++) d_bs[jj] = 256;
    }
}

// ============================ IIR (warp-parallel affine scan) ================
// kind==1 (deg) output is stored pre-shifted: dst[t] = y[t+1]; dst[TLEN-1]=y[TLEN-1].
__global__ void k_iir(const float* __restrict__ deg_in, const float* __restrict__ ref_in) {
    int gw = (blockIdx.x * blockDim.x + threadIdx.x) >> 5;
    int lane = threadIdx.x & 31;
    int sig = gw / NCH;
    int ch = gw % NCH;
    if (sig >= 2 * NBATCH) return;
    int kind = sig & 1;
    int b = sig >> 1;
    const float* src = (kind == 0) ? deg_in + (size_t)b * TLEN : ref_in + (size_t)b * TLEN;
    const float scale = (kind == 0) ? 32320.01953125f : 23455.2265625f;
    float* dst = &g_filt[kind][b][0];
    const int t0 = ch * CHUNK;

    auto ld = [&](int t) -> float {
        float v = src[t] * scale;
        if (t < 15)               v *= (float)(t + 1) * 0.0625f;
        else if (t >= TLEN - 15)  v *= (float)(TLEN - t) * 0.0625f;
        return v;
    };

    float c0 = 0.f, c1 = 0.f;
    if (t0 > 0) {
        float a0 = 0.f, a1 = 0.f;
        #pragma unroll
        for (int it = 0; it < 32; it++) {
            int d = it * 32 + lane;
            float xv = ld(t0 - 1 - d);
            a0 += d_hw[d][0] * xv;
            a1 += d_hw[d][1] * xv;
        }
        c0 = wredsum(a0);
        c1 = wredsum(a1);
    }

    const float B0 = 2.740826f;
    const float A00 = d_A64[0], A01 = d_A64[1], A10 = d_A64[2], A11 = d_A64[3];
    const int i0 = 2 * lane, i1 = 2 * lane + 1;
    const float g00 = d_g64[i0][0], g01 = d_g64[i0][1];
    const float g10 = d_g64[i1][0], g11 = d_g64[i1][1];
    const float r00 = d_r064[i0][0], r01 = d_r064[i0][1];
    const float r10 = d_r064[i1][0], r11 = d_r064[i1][1];

    for (int blk = 0; blk < CHUNK / 64; blk++) {
        int base = t0 + blk * 64;
        int ta = base + i0;
        float x0 = ld(ta), x1 = ld(ta + 1);
        float u0 = g00 * x0 + g10 * x1;
        float u1 = g01 * x0 + g11 * x1;
        float p0 = u0, p1 = u1;
        #pragma unroll
        for (int d = 1; d < 32; d <<= 1) {
            float v0 = __shfl_up_sync(FULLM, p0, d);
            float v1 = __shfl_up_sync(FULLM, p1, d);
            if (lane >= d) { p0 += v0; p1 += v1; }
        }
        float tot0 = __shfl_sync(FULLM, p0, 31);
        float tot1 = __shfl_sync(FULLM, p1, 31);
        float e0 = p0 - u0, e1 = p1 - u1;
        float P0 = c0 + e0, P1 = c1 + e1;
        float y0 = B0 * x0 + (r00 * P0 + r01 * P1);
        float Q0 = P0 + g00 * x0, Q1 = P1 + g01 * x0;
        float y1 = B0 * x1 + (r10 * Q0 + r11 * Q1);
        if (kind == 0) {
            *reinterpret_cast<float2*>(dst + ta) = make_float2(y0, y1);
        } else {
            if (ta > 0) dst[ta - 1] = y0;
            dst[ta] = y1;
            if (ta + 1 == TLEN - 1) dst[TLEN - 1] = y1;
        }
        float n0 = c0 + tot0, n1 = c1 + tot1;
        c0 = A00 * n0 + A01 * n1;
        c1 = A10 * n0 + A11 * n1;
    }
}

// ============================ spectrogram + bark (warp FFT) ==================
// 256-pt complex FFT of packed real data, per warp: 256 = 8(reg) x 32(lane).
// Direct float4 gmem loads into packed layout; conjugate unpack via shfl.
__global__ void __launch_bounds__(256) k_spec() {
    const int lane = threadIdx.x & 31;
    const int wrp = threadIdx.x >> 5;
    const int task = blockIdx.x * 8 + wrp;       // 2*64*156 = 19968 tasks
    const int FG = NFRAMES / FPW;                // 156
    int tmp = task;
    const int fg = tmp % FG; tmp /= FG;
    const int b = tmp % NBATCH; tmp /= NBATCH;
    const int kind = tmp;

    __shared__ float sm[8][256];
    float* S = sm[wrp];

    const int k2 = __brev(lane) >> 27;           // bitrev5(lane)
    // cross-lane stage twiddles: stage s, span d=16>>s, W_{2d}^{lane & (d-1)}
    float twc[5], tws[5];
    #pragma unroll
    for (int s = 0; s < 5; s++) {
        int d = 16 >> s;
        sincospif(-(float)(lane & (d - 1)) / (float)d, &tws[s], &twc[s]);
    }
    float wc, ws;  sincospif(-(float)k2 / 128.0f, &ws, &wc);   // W256^{k2}
    float uc, us;  sincospif(-(float)k2 / 256.0f, &us, &uc);   // e^{-i pi k2/256}
    const int ln = __brev((32 - k2) & 31) >> 27; // lane holding conj partner (k2>0); ln=0 for lane 0

    const int   BRT3[8] = {0, 4, 2, 6, 1, 5, 3, 7};
    constexpr int J0[8] = {0, 1, 3, 2, 7, 6, 5, 4};  // lane-0 conj slot permutation
    const float C8[8]  = {1.f, 0.92387953f, 0.70710678f, 0.38268343f, 0.f, -0.38268343f, -0.70710678f, -0.92387953f};
    const float S8n[8] = {0.f, -0.38268343f, -0.70710678f, -0.92387953f, -1.f, -0.92387953f, -0.70710678f, -0.38268343f};
    const float R2 = 0.70710678f;

    // Hann factors for this lane's 16 samples (lane-constant across frames)
    float2 h[8];
    #pragma unroll
    for (int j = 0; j < 8; j++) {
        int n = 16 * lane + 2 * j;
        h[j].x = d_hann[n]; h[j].y = d_hann[n + 1];
    }

    const float* sig = &g_filt[kind][b][0];

    for (int fi = 0; fi < FPW; fi++) {
        const int f = fg * FPW + fi;
        const float4* f4 = reinterpret_cast<const float4*>(sig + f * 256);

        // ---- direct packed load: v[j] = (x[16l+2j], x[16l+2j+1]) * hann ----
        float2 v[8];
        #pragma unroll
        for (int m = 0; m < 4; m++) {
            float4 q = f4[lane * 4 + m];
            v[2*m].x   = q.x * h[2*m].x;   v[2*m].y   = q.y * h[2*m].y;
            v[2*m+1].x = q.z * h[2*m+1].x; v[2*m+1].y = q.w * h[2*m+1].y;
        }

        // ---- cross-lane 32-pt DIF (per slot) ----
        #pragma unroll
        for (int s = 0; s < 5; s++) {
            int d = 16 >> s;
            bool up = (lane & d) != 0;
            float tc = twc[s], ts_ = tws[s];
            #pragma unroll
            for (int j = 0; j < 8; j++) {
                float ox = __shfl_xor_sync(FULLM, v[j].x, d);
                float oy = __shfl_xor_sync(FULLM, v[j].y, d);
                if (up) {
                    float rx = ox - v[j].x, ry = oy - v[j].y;
                    v[j].x = rx * tc - ry * ts_;
                    v[j].y = rx * ts_ + ry * tc;
                } else { v[j].x += ox; v[j].y += oy; }
            }
        }

        // ---- twiddle W256^{n1*k2}, cumulative ----
        {
            float cc = wc, cs_ = ws;
            #pragma unroll
            for (int j = 1; j < 8; j++) {
                float nx = v[j].x * cc - v[j].y * cs_;
                float ny = v[j].x * cs_ + v[j].y * cc;
                v[j].x = nx; v[j].y = ny;
                if (j < 7) { float t0 = cc * wc - cs_ * ws; cs_ = cc * ws + cs_ * wc; cc = t0; }
            }
        }

        // ---- in-register 8-pt DIF over slots ----
        {
            float tx, ty;
            tx = v[0].x - v[4].x; ty = v[0].y - v[4].y; v[0].x += v[4].x; v[0].y += v[4].y; v[4].x = tx; v[4].y = ty;
            tx = v[1].x - v[5].x; ty = v[1].y - v[5].y; v[1].x += v[5].x; v[1].y += v[5].y;
            v[5].x = R2 * (tx + ty); v[5].y = R2 * (ty - tx);
            tx = v[2].x - v[6].x; ty = v[2].y - v[6].y; v[2].x += v[6].x; v[2].y += v[6].y;
            v[6].x = ty; v[6].y = -tx;
            tx = v[3].x - v[7].x; ty = v[3].y - v[7].y; v[3].x += v[7].x; v[3].y += v[7].y;
            v[7].x = R2 * (ty - tx); v[7].y = -R2 * (tx + ty);
            #pragma unroll
            for (int g = 0; g < 8; g += 4) {
                tx = v[g].x - v[g+2].x; ty = v[g].y - v[g+2].y; v[g].x += v[g+2].x; v[g].y += v[g+2].y; v[g+2].x = tx; v[g+2].y = ty;
                tx = v[g+1].x - v[g+3].x; ty = v[g+1].y - v[g+3].y; v[g+1].x += v[g+3].x; v[g+1].y += v[g+3].y;
                v[g+3].x = ty; v[g+3].y = -tx;   // * (-i)
            }
            #pragma unroll
            for (int g = 0; g < 8; g += 2) {
                tx = v[g].x - v[g+1].x; ty = v[g].y - v[g+1].y; v[g].x += v[g+1].x; v[g].y += v[g+1].y; v[g+1].x = tx; v[g+1].y = ty;
            }
        }
        // slot j holds Z[32*BRT3[j] + k2]

        // ---- unpack real FFT + power (conjugate partner via shfl) ----
        float p[8];
        #pragma unroll
        for (int j = 0; j < 8; j++) {
            int k1 = BRT3[j];
            int kk = 32 * k1 + k2;
            // Z[(256-kk)&255]: lane ln, slot 7-j  (lane 0: own slot J0[j])
            float znr = __shfl_sync(FULLM, v[7 - j].x, ln);
            float zni = __shfl_sync(FULLM, v[7 - j].y, ln);
            if (lane == 0) { znr = v[J0[j]].x; zni = v[J0[j]].y; }
            float Ex = 0.5f * (v[j].x + znr), Ey = 0.5f * (v[j].y - zni);
            float Ox = 0.5f * (v[j].y + zni), Oy = -0.5f * (v[j].x - znr);
            float tc = uc * C8[k1] - us * S8n[k1];
            float ts_ = uc * S8n[k1] + us * C8[k1];
            float wox = Ox * tc - Oy * ts_;
            float woy = Ox * ts_ + Oy * tc;
            float Xr = Ex + wox, Xi = Ey + woy;
            float pw = Xr * Xr + Xi * Xi;
            p[j] = (kk == 0) ? 0.f : pw;          // bin 0 zeroed
        }
        #pragma unroll
        for (int j = 0; j < 8; j++) S[32 * BRT3[j] + k2] = p[j];
        __syncwarp();

        // ---- contiguous band sums (no atomics) ----
        float acc0 = 0.f, acc1 = 0.f;
        {
            int s0 = d_bs[lane], e0 = d_bs[lane + 1];
            for (int i = s0; i < e0; i++) acc0 += S[i];
            if (lane < 17) {
                int s1 = d_bs[32 + lane], e1 = d_bs[33 + lane];
                for (int i = s1; i < e1; i++) acc1 += S[i];
            }
        }
        float v0 = acc0 * d_powcorr[lane];
        g_bark[kind][b][f][lane] = v0;
        float v1 = 0.f;
        if (lane < 17) {
            v1 = acc1 * d_powcorr[32 + lane];
            g_bark[kind][b][f][32 + lane] = v1;
        }

        // ---- silent detection fused (ref path only) ----
        if (kind == 0) {
            float sa = (lane >= 1 && v0 > d_thresh[lane] * 100.f) ? v0 : 0.f;
            if (lane < 17 && v1 > d_thresh[32 + lane] * 100.f) sa += v1;
            sa = wredsum(sa);
            if (lane == 0) {
                int sil = sa < 1e7f;
                g_silent[b][f] = sil;
                if (!sil) atomicAdd(&g_cnt[b], 1);
            }
        }
        __syncwarp();
    }
}

// ============================ time-avg partial sums ==========================
__global__ void k_tsum() {
    int b = blockIdx.x, slab = blockIdx.y;
    int t = threadIdx.x;
    int n = t & 63, fi = t >> 6;
    bool act = n < NBANDS;
    float ad = 0.f, ar = 0.f;
    int f0 = slab * FSLAB;
    if (act) {
        float th100 = d_thresh[n] * 100.f;
        for (int f = f0 + fi; f < f0 + FSLAB; f += 4) {
            if (!g_silent[b][f]) {
                float dv = g_bark[1][b][f][n];
                if (dv > th100) ad += dv;
                float rv = g_bark[0][b][f][n];
                if (rv > th100) ar += rv;
            }
        }
    }
    __shared__ float sd[4][64], sr[4][64];
    sd[fi][n] = ad; sr[fi][n] = ar;
    __syncthreads();
    if (fi == 0 && act) {
        atomicAdd(&g_accd[b][n], sd[0][n] + sd[1][n] + sd[2][n] + sd[3][n]);
        atomicAdd(&g_accr[b][n], sr[0][n] + sr[1][n] + sr[2][n] + sr[3][n]);
    }
}

// ============================ dist (fpr + bpr fused, 4-frame strips) =========
__device__ __forceinline__ float loudf(float x, float th, float g) {
    if (x > th)
        return 1.866055e-1f * g * (__powf(0.5f + 0.5f * x / th, 0.23f) - 1.f);
    return 0.f;
}

__global__ void k_dist() {
    int gw = (blockIdx.x * blockDim.x + threadIdx.x) >> 5;
    int lane = threadIdx.x & 31;
    const int NG = NFRAMES / DFR;   // 156
    if (gw >= NBATCH * NG) return;
    int b = gw / NG, fg = gw % NG;
    int f0 = fg * DFR;
    bool has1 = lane < 17;
    int n0 = lane, n1 = lane + 32;

    float cntInv = 1.f / (float)max(g_cnt[b], 1);
    float th0 = d_thresh[n0], th1 = has1 ? d_thresh[n1] : 1.f;
    float bpr0, bpr1 = 0.f;
    {
        float md = g_accd[b][n0] * cntInv, mr = g_accr[b][n0] * cntInv;
        bpr0 = fminf(fmaxf((md + 1000.f) / (mr + 1000.f), 0.01f), 100.f);
        if (has1) {
            float md1 = g_accd[b][n1] * cntInv, mr1 = g_accr[b][n1] * cntInv;
            bpr1 = fminf(fmaxf((md1 + 1000.f) / (mr1 + 1000.f), 0.01f), 100.f);
        }
    }
    float g0 = d_g023[n0], g1 = has1 ? d_g023[n1] : 1.f;
    float w0 = d_w0, wsum = d_wsum;

    float R0[DFR], D0[DFR], R1[DFR], D1[DFR], TA[DFR], RT[DFR + 1];

    // boundary frame f0-1 (ratio only)
    if (f0 > 0) {
        int f = f0 - 1;
        float r0 = g_bark[0][b][f][n0], d0 = g_bark[1][b][f][n0];
        float r1 = has1 ? g_bark[0][b][f][n1] : 0.f;
        float d1 = has1 ? g_bark[1][b][f][n1] : 0.f;
        float e0 = bpr0 * r0, e1 = bpr1 * r1;
        float taeq = ((n0 >= 1 && e0 > th0) ? e0 : 0.f) + ((has1 && e1 > th1) ? e1 : 0.f);
        float tad  = ((n0 >= 1 && d0 > th0) ? d0 : 0.f) + ((has1 && d1 > th1) ? d1 : 0.f);
        taeq = wredsum(taeq);
        tad  = wredsum(tad);
        RT[0] = (taeq + 5000.f) / (tad + 5000.f);
    } else RT[0] = 0.f;

    #pragma unroll
    for (int k = 0; k < DFR; k++) {
        int f = f0 + k;
        R0[k] = g_bark[0][b][f][n0]; D0[k] = g_bark[1][b][f][n0];
        R1[k] = has1 ? g_bark[0][b][f][n1] : 0.f;
        D1[k] = has1 ? g_bark[1][b][f][n1] : 0.f;
        float e0 = bpr0 * R0[k], e1 = bpr1 * R1[k];
        float taeq = ((n0 >= 1 && e0 > th0) ? e0 : 0.f) + ((has1 && e1 > th1) ? e1 : 0.f);
        float tad  = ((n0 >= 1 && D0[k] > th0) ? D0[k] : 0.f) + ((has1 && D1[k] > th1) ? D1[k] : 0.f);
        taeq = wredsum(taeq);
        tad  = wredsum(tad);
        TA[k] = taeq;
        RT[k + 1] = (taeq + 5000.f) / (tad + 5000.f);
    }

    #pragma unroll
    for (int k = 0; k < DFR; k++) {
        int f = f0 + k;
        float fp = RT[k + 1];
        if (f > 0) fp = 0.8f * fp + 0.2f * RT[k];
        fp = fminf(fmaxf(fp, 0.0003f), 5.0f);

        float acc2 = 0.f, acc1 = 0.f;
        {
            float eqr0 = bpr0 * R0[k];
            float eqd0 = fp * D0[k];
            float dl = loudf(eqd0, th0, g0);
            float rl = loudf(eqr0, th0, g0);
            float di = dl - rl;
            float dz = 0.25f * fminf(dl, rl);
            float ad = fmaxf(fabsf(di) - dz, 0.f);
            float t2 = ad * w0;
            acc2 += t2 * t2;
            float as = __powf((eqd0 + 50.f) / (eqr0 + 50.f), 1.2f);
            as = (as < 3.f) ? 0.f : fminf(as, 12.f);
            acc1 += ad * as * w0;
        }
        if (has1) {
            float eqr1 = bpr1 * R1[k];
            float eqd1 = fp * D1[k];
            float dl = loudf(eqd1, th1, g1);
            float rl = loudf(eqr1, th1, g1);
            float di = dl - rl;
            float dz = 0.25f * fminf(dl, rl);
            float ad = fmaxf(fabsf(di) - dz, 0.f);
            float t2 = ad * w0;
            acc2 += t2 * t2;
            float as = __powf((eqd1 + 50.f) / (eqr1 + 50.f), 1.2f);
            as = (as < 3.f) ? 0.f : fminf(as, 12.f);
            acc1 += ad * as * w0;
        }
        acc2 = wredsum(acc2);
        acc1 = wredsum(acc1);
        if (lane == 0) {
            float symm = fmaxf(sqrtf(acc2 / wsum) * wsum, 1e-20f);
            float asym = fmaxf(acc1, 1e-20f);
            float h = __powf((TA[k] + 1e5f) * 1e-7f, 0.04f);
            g_symm[b][f] = fminf(symm / h, 45.f);
            g_asym[b][f] = fminf(asym / h, 45.f);
        }
    }
}

// ============================ psqm + mos =====================================
__global__ void k_psqm(float* __restrict__ out) {
    int b = blockIdx.x, t = threadIdx.x;   // 64 threads
    float accS = 0.f, accA = 0.f;
    if (t < 61) {
        int base = t * 10;
        float m6s = 0.f, m6a = 0.f;
        #pragma unroll
        for (int i = 0; i < 20; i++) {
            float xs = g_symm[b][base + i];
            float x2 = xs * xs;
            m6s += x2 * x2 * x2;
            float xa = g_asym[b][base + i];
            float y2 = xa * xa;
            m6a += y2 * y2 * y2;
        }
        accS = cbrtf(m6s * (1.f / 20.f));
        accA = cbrtf(m6a * (1.f / 20.f));
    }
    accS = wredsum(accS);
    accA = wredsum(accA);
    __shared__ float sS[2], sA[2];
    if ((t & 31) == 0) { sS[t >> 5] = accS; sA[t >> 5] = accA; }
    __syncthreads();
    if (t == 0) {
        float ds = sqrtf((sS[0] + sS[1]) / 61.f);
        float da = sqrtf((sA[0] + sA[1]) / 61.f);
        float mos = 4.5f - 0.1f * ds - 0.0309f * da;
        mos = 0.999f + 4.f / (1.f + expf(-1.3669f * mos + 3.8224f));
        out[b] = 0.5f * (4.5f - mos);
    }
}

// ============================ launch =========================================
extern "C" void kernel_launch(void* const* d_in, const int* in_sizes, int n_in,
                              void* d_out, int out_size) {
    const float* deg = (const float*)d_in[0];
    const float* ref = (const float*)d_in[1];
    float* out = (float*)d_out;

    k_init<<<1, 1024>>>();

    {   // IIR: 128 signals * 50 chunks = 6400 warps
        int warps = 2 * NBATCH * NCH;
        k_iir<<<warps * 32 / 256, 256>>>(deg, ref);
    }
    {   // spec: 2*64*156 warp-tasks, 8 warps/block
        int tasks = 2 * NBATCH * (NFRAMES / FPW);
        k_spec<<<tasks / 8, 256>>>();
    }
    {
        dim3 gs(NBATCH, NSLAB);
        k_tsum<<<gs, 256>>>();
    }
    {   // dist: 64*156 warp-strips of 4 frames
        int warps = NBATCH * (NFRAMES / DFR);
        k_dist<<<warps * 32 / 256, 256>>>();
    }
    k_psqm<<<NBATCH, 64>>>(out);
}

// round 6
// speedup vs baseline: 1.6292x; 1.0452x over previous
#include <cuda_runtime.h>
#include <math.h>

#define TLEN    160000
#define NBATCH  64
#define NFRAMES 624
#define NBANDS  49
#define CHUNK   3200
#define NCH     (TLEN/CHUNK)   // 50
#define WARM    512            // IIR warmup taps (r^512 ~ 6.6e-7)
#define FPW     8              // frames per warp in k_spec
#define DFR     4              // frames per warp in k_dist
#define NSLAB   8              // frame slabs in k_tsum (624 = 8*78)
#define FSLAB   (NFRAMES/NSLAB)
#define FULLM   0xffffffffu

// ---------------- persistent device buffers ----------------------------------
__device__ float g_filt[2][NBATCH][TLEN];           // 0 = ref; 1 = deg (stored pre-shifted by 1)
__device__ float g_bark[2][NBATCH][NFRAMES][NBANDS];
__device__ int   g_silent[NBATCH][NFRAMES];
__device__ int   g_cnt[NBATCH];
__device__ float g_accd[NBATCH][NBANDS];
__device__ float g_accr[NBATCH][NBANDS];
__device__ float g_symm[NBATCH][NFRAMES];
__device__ float g_asym[NBATCH][NFRAMES];

// ---------------- tables ------------------------------------------------------
__device__ float d_hw[WARM][2];    // A^d * c
__device__ float d_g64[64][2];     // A^{-1-i} * c
__device__ float d_r064[64][2];    // row 0 of A^m
__device__ float d_A64[4];         // A^64
__device__ int   d_band[256];
__device__ int   d_bs[50];         // band start bins (contiguous ranges)
__device__ float d_powcorr[NBANDS];
__device__ float d_thresh[NBANDS];
__device__ float d_g023[NBANDS];
__device__ float d_hann[512];
__device__ float d_w0, d_wsum;

__device__ __forceinline__ float wredsum(float v) {
    #pragma unroll
    for (int o = 16; o; o >>= 1) v += __shfl_xor_sync(FULLM, v, o);
    return v;
}

// ============================ table init =====================================
// u_d = r^{d-1} sin(d*theta)/sin(theta); angle reduced in double, eval in float.
__device__ __forceinline__ float u_fast(float d, double theta, float lnr, float sinv) {
    double ang = (double)d * theta;
    double k = rint(ang * 0.15915494309189533576888376337251);
    float a = (float)(ang - k * 6.283185307179586476925286766559);
    return __expf((d - 1.0f) * lnr) * __sinf(a) * sinv;
}

__global__ void k_init() {
    int t = threadIdx.x;           // 1024 threads, ONE block
    __shared__ int s_cnt[NBANDS];
    __shared__ double sh_theta;
    __shared__ float sh_lnr, sh_sinv, sh_k1, sh_k2, sh_k3, sh_P, sh_Q;
    if (t < NBANDS) s_cnt[t] = 0;
    if (t == 0) {
        const double P = 1.9444777, Q = 0.94597794;
        const double B0 = 2.740826, B1 = -5.4816519, B2 = 2.740826;
        double c0 = B1 + P * B0;          // cancellation -> keep double
        double c1 = B2 - Q * B0;
        double s = sqrt(4.0 * Q - P * P);
        double theta = atan2(s, P);
        sh_theta = theta;
        sh_lnr  = (float)(0.5 * log(Q));
        sh_sinv = (float)(1.0 / sin(theta));
        sh_k1 = (float)(P * c0 + c1);
        sh_k2 = (float)(Q * c0);
        sh_k3 = (float)(Q * c1);
        sh_P = (float)P; sh_Q = (float)Q;
    }
    __syncthreads();

    const double maxbark = 7.0 * asinh(8000.0 / 650.0);
    const double step = maxbark / 49.0;

    if (t < 256) {
        double f = (t + 0.5) * (16000.0 / 512.0);
        double bark = 7.0 * asinh(f / 650.0);
        int idx = 0;
        for (int j = 0; j <= 49; j++) {
            double e = (j == 49) ? maxbark : step * j;
            if (e <= bark) idx = j + 1;
        }
        int band = min(max(idx - 1, 0), 48);
        d_band[t] = band;
        atomicAdd(&s_cnt[band], 1);
    }
    if (t < 512)
        d_hann[t] = 0.5f - 0.5f * cospif((float)t / 256.0f);
    if (t < NBATCH) g_cnt[t] = 0;
    for (int i = t; i < NBATCH * NBANDS; i += 1024) {
        (&g_accd[0][0])[i] = 0.f;
        (&g_accr[0][0])[i] = 0.f;
    }
    __syncthreads();

    if (t < NBANDS) {
        float cnt = s_cnt[t] > 1 ? (float)s_cnt[t] : 1.0f;
        d_powcorr[t] = 6.910853e-6f * 100.0f / cnt;
        float e0 = (float)(step * t);
        float e1 = (t == 48) ? (float)maxbark : (float)(step * (t + 1));
        float fc = 650.0f * sinhf(0.5f * (e0 + e1) / 7.0f);
        fc = fmaxf(fc, 20.0f) * 0.001f;
        float ath = 3.64f * powf(fc, -0.8f)
                  - 6.5f * expf(-0.6f * (fc - 3.3f) * (fc - 3.3f))
                  + 1e-3f * powf(fc, 4.0f);
        float thv = exp10f(ath * 0.1f);
        d_thresh[t] = thv;
        d_g023[t] = powf(thv * 2.0f, 0.23f);
    }

    double th_ = sh_theta;
    float lnr = sh_lnr, sinv = sh_sinv;
    float k1 = sh_k1, k2 = sh_k2, k3 = sh_k3, Pf = sh_P, Qf = sh_Q;

    if (t < WARM) {
        float u  = u_fast((float)t, th_, lnr, sinv);
        float um = u_fast((float)t - 1.f, th_, lnr, sinv);
        d_hw[t][0] = u * k1 - um * k2;
        d_hw[t][1] = -u * k2 - um * k3;
    }
    if (t < 64) {
        float d = -1.f - (float)t;
        float u  = u_fast(d, th_, lnr, sinv);
        float um = u_fast(d - 1.f, th_, lnr, sinv);
        d_g64[t][0] = u * k1 - um * k2;
        d_g64[t][1] = -u * k2 - um * k3;
        float m = (float)t;
        float uM  = u_fast(m, th_, lnr, sinv);
        float uMm = u_fast(m - 1.f, th_, lnr, sinv);
        d_r064[t][0] = uM * Pf - Qf * uMm;
        d_r064[t][1] = uM;
    }
    if (t == 0) {
        float u64 = u_fast(64.f, th_, lnr, sinv);
        float u63 = u_fast(63.f, th_, lnr, sinv);
        d_A64[0] = u64 * Pf - Qf * u63;
        d_A64[1] = u64;
        d_A64[2] = -Qf * u64;
        d_A64[3] = -Qf * u63;

        float w0f = (float)step;
        float ws = 0.f;
        for (int i = 0; i < 49; i++) ws += w0f;
        d_w0 = w0f; d_wsum = ws;

        // band start table (bands are contiguous bin ranges)
        d_bs[0] = 0;
        for (int k = 1; k < 256; k++)
            if (d_band[k] != d_band[k - 1])
                for (int jj = d_band[k - 1] + 1; jj <= d_band[k]; jj++) d_bs[jj] = k;
        for (int jj = d_band[255] + 1; jj <= 49; jj++) d_bs[jj] = 256;
    }
}

// ============================ IIR (warp-parallel affine scan) ================
// kind==1 (deg) output is stored pre-shifted: dst[t] = y[t+1]; dst[TLEN-1]=y[TLEN-1].
__global__ void k_iir(const float* __restrict__ deg_in, const float* __restrict__ ref_in) {
    int gw = (blockIdx.x * blockDim.x + threadIdx.x) >> 5;
    int lane = threadIdx.x & 31;
    int sig = gw / NCH;
    int ch = gw % NCH;
    if (sig >= 2 * NBATCH) return;
    int kind = sig & 1;
    int b = sig >> 1;
    const float* src = (kind == 0) ? deg_in + (size_t)b * TLEN : ref_in + (size_t)b * TLEN;
    const float scale = (kind == 0) ? 32320.01953125f : 23455.2265625f;
    float* dst = &g_filt[kind][b][0];
    const int t0 = ch * CHUNK;

    auto ld = [&](int t) -> float {
        float v = src[t] * scale;
        if (t < 15)               v *= (float)(t + 1) * 0.0625f;
        else if (t >= TLEN - 15)  v *= (float)(TLEN - t) * 0.0625f;
        return v;
    };

    float c0 = 0.f, c1 = 0.f;
    if (t0 > 0) {
        float a0 = 0.f, a1 = 0.f;
        #pragma unroll
        for (int it = 0; it < WARM / 32; it++) {
            int d = it * 32 + lane;
            float xv = ld(t0 - 1 - d);
            a0 += d_hw[d][0] * xv;
            a1 += d_hw[d][1] * xv;
        }
        c0 = wredsum(a0);
        c1 = wredsum(a1);
    }

    const float B0 = 2.740826f;
    const float A00 = d_A64[0], A01 = d_A64[1], A10 = d_A64[2], A11 = d_A64[3];
    const int i0 = 2 * lane, i1 = 2 * lane + 1;
    const float g00 = d_g64[i0][0], g01 = d_g64[i0][1];
    const float g10 = d_g64[i1][0], g11 = d_g64[i1][1];
    const float r00 = d_r064[i0][0], r01 = d_r064[i0][1];
    const float r10 = d_r064[i1][0], r11 = d_r064[i1][1];

    for (int blk = 0; blk < CHUNK / 64; blk++) {
        int base = t0 + blk * 64;
        int ta = base + i0;
        float x0 = ld(ta), x1 = ld(ta + 1);
        float u0 = g00 * x0 + g10 * x1;
        float u1 = g01 * x0 + g11 * x1;
        float p0 = u0, p1 = u1;
        #pragma unroll
        for (int d = 1; d < 32; d <<= 1) {
            float v0 = __shfl_up_sync(FULLM, p0, d);
            float v1 = __shfl_up_sync(FULLM, p1, d);
            if (lane >= d) { p0 += v0; p1 += v1; }
        }
        float tot0 = __shfl_sync(FULLM, p0, 31);
        float tot1 = __shfl_sync(FULLM, p1, 31);
        float e0 = p0 - u0, e1 = p1 - u1;
        float P0 = c0 + e0, P1 = c1 + e1;
        float y0 = B0 * x0 + (r00 * P0 + r01 * P1);
        float Q0 = P0 + g00 * x0, Q1 = P1 + g01 * x0;
        float y1 = B0 * x1 + (r10 * Q0 + r11 * Q1);
        if (kind == 0) {
            *reinterpret_cast<float2*>(dst + ta) = make_float2(y0, y1);
        } else {
            if (ta > 0) dst[ta - 1] = y0;
            dst[ta] = y1;
            if (ta + 1 == TLEN - 1) dst[TLEN - 1] = y1;
        }
        float n0 = c0 + tot0, n1 = c1 + tot1;
        c0 = A00 * n0 + A01 * n1;
        c1 = A10 * n0 + A11 * n1;
    }
}

// ============================ spectrogram + bark (warp FFT) ==================
// 256-pt complex FFT of packed real data, per warp: 256 = 8(reg) x 32(lane).
// Direct float4 gmem loads into packed layout; conjugate unpack via shfl.
__global__ void __launch_bounds__(256) k_spec() {
    const int lane = threadIdx.x & 31;
    const int wrp = threadIdx.x >> 5;
    const int task = blockIdx.x * 8 + wrp;       // 2*64*78 = 9984 tasks
    const int FG = NFRAMES / FPW;                // 78
    int tmp = task;
    const int fg = tmp % FG; tmp /= FG;
    const int b = tmp % NBATCH; tmp /= NBATCH;
    const int kind = tmp;

    __shared__ float sm[8][256];
    float* S = sm[wrp];

    const int k2 = __brev(lane) >> 27;           // bitrev5(lane)
    // cross-lane stage twiddles: stage s, span d=16>>s, W_{2d}^{lane & (d-1)}
    float twc[5], tws[5];
    #pragma unroll
    for (int s = 0; s < 5; s++) {
        int d = 16 >> s;
        sincospif(-(float)(lane & (d - 1)) / (float)d, &tws[s], &twc[s]);
    }
    float wc, ws;  sincospif(-(float)k2 / 128.0f, &ws, &wc);   // W256^{k2}
    float uc, us;  sincospif(-(float)k2 / 256.0f, &us, &uc);   // e^{-i pi k2/256}
    const int ln = __brev((32 - k2) & 31) >> 27; // lane holding conj partner (k2>0); ln=0 for lane 0

    const int   BRT3[8] = {0, 4, 2, 6, 1, 5, 3, 7};
    constexpr int J0[8] = {0, 1, 3, 2, 7, 6, 5, 4};  // lane-0 conj slot permutation
    const float C8[8]  = {1.f, 0.92387953f, 0.70710678f, 0.38268343f, 0.f, -0.38268343f, -0.70710678f, -0.92387953f};
    const float S8n[8] = {0.f, -0.38268343f, -0.70710678f, -0.92387953f, -1.f, -0.92387953f, -0.70710678f, -0.38268343f};
    const float R2 = 0.70710678f;

    // Hann factors for this lane's 16 samples (lane-constant across frames)
    float2 h[8];
    #pragma unroll
    for (int j = 0; j < 8; j++) {
        int n = 16 * lane + 2 * j;
        h[j].x = d_hann[n]; h[j].y = d_hann[n + 1];
    }

    const float* sig = &g_filt[kind][b][0];

    for (int fi = 0; fi < FPW; fi++) {
        const int f = fg * FPW + fi;
        const float4* f4 = reinterpret_cast<const float4*>(sig + f * 256);

        // ---- direct packed load: v[j] = (x[16l+2j], x[16l+2j+1]) * hann ----
        float2 v[8];
        #pragma unroll
        for (int m = 0; m < 4; m++) {
            float4 q = f4[lane * 4 + m];
            v[2*m].x   = q.x * h[2*m].x;   v[2*m].y   = q.y * h[2*m].y;
            v[2*m+1].x = q.z * h[2*m+1].x; v[2*m+1].y = q.w * h[2*m+1].y;
        }

        // ---- cross-lane 32-pt DIF (per slot) ----
        #pragma unroll
        for (int s = 0; s < 5; s++) {
            int d = 16 >> s;
            bool up = (lane & d) != 0;
            float tc = twc[s], ts_ = tws[s];
            #pragma unroll
            for (int j = 0; j < 8; j++) {
                float ox = __shfl_xor_sync(FULLM, v[j].x, d);
                float oy = __shfl_xor_sync(FULLM, v[j].y, d);
                if (up) {
                    float rx = ox - v[j].x, ry = oy - v[j].y;
                    v[j].x = rx * tc - ry * ts_;
                    v[j].y = rx * ts_ + ry * tc;
                } else { v[j].x += ox; v[j].y += oy; }
            }
        }

        // ---- twiddle W256^{n1*k2}, cumulative ----
        {
            float cc = wc, cs_ = ws;
            #pragma unroll
            for (int j = 1; j < 8; j++) {
                float nx = v[j].x * cc - v[j].y * cs_;
                float ny = v[j].x * cs_ + v[j].y * cc;
                v[j].x = nx; v[j].y = ny;
                if (j < 7) { float t0 = cc * wc - cs_ * ws; cs_ = cc * ws + cs_ * wc; cc = t0; }
            }
        }

        // ---- in-register 8-pt DIF over slots ----
        {
            float tx, ty;
            tx = v[0].x - v[4].x; ty = v[0].y - v[4].y; v[0].x += v[4].x; v[0].y += v[4].y; v[4].x = tx; v[4].y = ty;
            tx = v[1].x - v[5].x; ty = v[1].y - v[5].y; v[1].x += v[5].x; v[1].y += v[5].y;
            v[5].x = R2 * (tx + ty); v[5].y = R2 * (ty - tx);
            tx = v[2].x - v[6].x; ty = v[2].y - v[6].y; v[2].x += v[6].x; v[2].y += v[6].y;
            v[6].x = ty; v[6].y = -tx;
            tx = v[3].x - v[7].x; ty = v[3].y - v[7].y; v[3].x += v[7].x; v[3].y += v[7].y;
            v[7].x = R2 * (ty - tx); v[7].y = -R2 * (tx + ty);
            #pragma unroll
            for (int g = 0; g < 8; g += 4) {
                tx = v[g].x - v[g+2].x; ty = v[g].y - v[g+2].y; v[g].x += v[g+2].x; v[g].y += v[g+2].y; v[g+2].x = tx; v[g+2].y = ty;
                tx = v[g+1].x - v[g+3].x; ty = v[g+1].y - v[g+3].y; v[g+1].x += v[g+3].x; v[g+1].y += v[g+3].y;
                v[g+3].x = ty; v[g+3].y = -tx;   // * (-i)
            }
            #pragma unroll
            for (int g = 0; g < 8; g += 2) {
                tx = v[g].x - v[g+1].x; ty = v[g].y - v[g+1].y; v[g].x += v[g+1].x; v[g].y += v[g+1].y; v[g+1].x = tx; v[g+1].y = ty;
            }
        }
        // slot j holds Z[32*BRT3[j] + k2]

        // ---- unpack real FFT + power (conjugate partner via shfl) ----
        float p[8];
        #pragma unroll
        for (int j = 0; j < 8; j++) {
            int k1 = BRT3[j];
            int kk = 32 * k1 + k2;
            // Z[(256-kk)&255]: lane ln, slot 7-j  (lane 0: own slot J0[j])
            float znr = __shfl_sync(FULLM, v[7 - j].x, ln);
            float zni = __shfl_sync(FULLM, v[7 - j].y, ln);
            if (lane == 0) { znr = v[J0[j]].x; zni = v[J0[j]].y; }
            float Ex = 0.5f * (v[j].x + znr), Ey = 0.5f * (v[j].y - zni);
            float Ox = 0.5f * (v[j].y + zni), Oy = -0.5f * (v[j].x - znr);
            float tc = uc * C8[k1] - us * S8n[k1];
            float ts_ = uc * S8n[k1] + us * C8[k1];
            float wox = Ox * tc - Oy * ts_;
            float woy = Ox * ts_ + Oy * tc;
            float Xr = Ex + wox, Xi = Ey + woy;
            float pw = Xr * Xr + Xi * Xi;
            p[j] = (kk == 0) ? 0.f : pw;          // bin 0 zeroed
        }
        #pragma unroll
        for (int j = 0; j < 8; j++) S[32 * BRT3[j] + k2] = p[j];
        __syncwarp();

        // ---- contiguous band sums (no atomics) ----
        float acc0 = 0.f, acc1 = 0.f;
        {
            int s0 = d_bs[lane], e0 = d_bs[lane + 1];
            for (int i = s0; i < e0; i++) acc0 += S[i];
            if (lane < 17) {
                int s1 = d_bs[32 + lane], e1 = d_bs[33 + lane];
                for (int i = s1; i < e1; i++) acc1 += S[i];
            }
        }
        float v0 = acc0 * d_powcorr[lane];
        g_bark[kind][b][f][lane] = v0;
        float v1 = 0.f;
        if (lane < 17) {
            v1 = acc1 * d_powcorr[32 + lane];
            g_bark[kind][b][f][32 + lane] = v1;
        }

        // ---- silent detection fused (ref path only) ----
        if (kind == 0) {
            float sa = (lane >= 1 && v0 > d_thresh[lane] * 100.f) ? v0 : 0.f;
            if (lane < 17 && v1 > d_thresh[32 + lane] * 100.f) sa += v1;
            sa = wredsum(sa);
            if (lane == 0) {
                int sil = sa < 1e7f;
                g_silent[b][f] = sil;
                if (!sil) atomicAdd(&g_cnt[b], 1);
            }
        }
        __syncwarp();
    }
}

// ============================ time-avg partial sums ==========================
__global__ void k_tsum() {
    int b = blockIdx.x, slab = blockIdx.y;
    int t = threadIdx.x;
    int n = t & 63, fi = t >> 6;
    bool act = n < NBANDS;
    float ad = 0.f, ar = 0.f;
    int f0 = slab * FSLAB;
    if (act) {
        float th100 = d_thresh[n] * 100.f;
        for (int f = f0 + fi; f < f0 + FSLAB; f += 4) {
            if (!g_silent[b][f]) {
                float dv = g_bark[1][b][f][n];
                if (dv > th100) ad += dv;
                float rv = g_bark[0][b][f][n];
                if (rv > th100) ar += rv;
            }
        }
    }
    __shared__ float sd[4][64], sr[4][64];
    sd[fi][n] = ad; sr[fi][n] = ar;
    __syncthreads();
    if (fi == 0 && act) {
        atomicAdd(&g_accd[b][n], sd[0][n] + sd[1][n] + sd[2][n] + sd[3][n]);
        atomicAdd(&g_accr[b][n], sr[0][n] + sr[1][n] + sr[2][n] + sr[3][n]);
    }
}

// ============================ dist (fpr + bpr fused, 4-frame strips) =========
__device__ __forceinline__ float loudf(float x, float th, float g) {
    if (x > th)
        return 1.866055e-1f * g * (__powf(0.5f + 0.5f * x / th, 0.23f) - 1.f);
    return 0.f;
}

__global__ void k_dist() {
    int gw = (blockIdx.x * blockDim.x + threadIdx.x) >> 5;
    int lane = threadIdx.x & 31;
    const int NG = NFRAMES / DFR;   // 156
    if (gw >= NBATCH * NG) return;
    int b = gw / NG, fg = gw % NG;
    int f0 = fg * DFR;
    bool has1 = lane < 17;
    int n0 = lane, n1 = lane + 32;

    float cntInv = 1.f / (float)max(g_cnt[b], 1);
    float th0 = d_thresh[n0], th1 = has1 ? d_thresh[n1] : 1.f;
    float bpr0, bpr1 = 0.f;
    {
        float md = g_accd[b][n0] * cntInv, mr = g_accr[b][n0] * cntInv;
        bpr0 = fminf(fmaxf((md + 1000.f) / (mr + 1000.f), 0.01f), 100.f);
        if (has1) {
            float md1 = g_accd[b][n1] * cntInv, mr1 = g_accr[b][n1] * cntInv;
            bpr1 = fminf(fmaxf((md1 + 1000.f) / (mr1 + 1000.f), 0.01f), 100.f);
        }
    }
    float g0 = d_g023[n0], g1 = has1 ? d_g023[n1] : 1.f;
    float w0 = d_w0, wsum = d_wsum;

    float R0[DFR], D0[DFR], R1[DFR], D1[DFR], TA[DFR], RT[DFR + 1];

    // boundary frame f0-1 (ratio only)
    if (f0 > 0) {
        int f = f0 - 1;
        float r0 = g_bark[0][b][f][n0], d0 = g_bark[1][b][f][n0];
        float r1 = has1 ? g_bark[0][b][f][n1] : 0.f;
        float d1 = has1 ? g_bark[1][b][f][n1] : 0.f;
        float e0 = bpr0 * r0, e1 = bpr1 * r1;
        float taeq = ((n0 >= 1 && e0 > th0) ? e0 : 0.f) + ((has1 && e1 > th1) ? e1 : 0.f);
        float tad  = ((n0 >= 1 && d0 > th0) ? d0 : 0.f) + ((has1 && d1 > th1) ? d1 : 0.f);
        taeq = wredsum(taeq);
        tad  = wredsum(tad);
        RT[0] = (taeq + 5000.f) / (tad + 5000.f);
    } else RT[0] = 0.f;

    #pragma unroll
    for (int k = 0; k < DFR; k++) {
        int f = f0 + k;
        R0[k] = g_bark[0][b][f][n0]; D0[k] = g_bark[1][b][f][n0];
        R1[k] = has1 ? g_bark[0][b][f][n1] : 0.f;
        D1[k] = has1 ? g_bark[1][b][f][n1] : 0.f;
        float e0 = bpr0 * R0[k], e1 = bpr1 * R1[k];
        float taeq = ((n0 >= 1 && e0 > th0) ? e0 : 0.f) + ((has1 && e1 > th1) ? e1 : 0.f);
        float tad  = ((n0 >= 1 && D0[k] > th0) ? D0[k] : 0.f) + ((has1 && D1[k] > th1) ? D1[k] : 0.f);
        taeq = wredsum(taeq);
        tad  = wredsum(tad);
        TA[k] = taeq;
        RT[k + 1] = (taeq + 5000.f) / (tad + 5000.f);
    }

    #pragma unroll
    for (int k = 0; k < DFR; k++) {
        int f = f0 + k;
        float fp = RT[k + 1];
        if (f > 0) fp = 0.8f * fp + 0.2f * RT[k];
        fp = fminf(fmaxf(fp, 0.0003f), 5.0f);

        float acc2 = 0.f, acc1 = 0.f;
        {
            float eqr0 = bpr0 * R0[k];
            float eqd0 = fp * D0[k];
            float dl = loudf(eqd0, th0, g0);
            float rl = loudf(eqr0, th0, g0);
            float di = dl - rl;
            float dz = 0.25f * fminf(dl, rl);
            float ad = fmaxf(fabsf(di) - dz, 0.f);
            float t2 = ad * w0;
            acc2 += t2 * t2;
            float as = __powf((eqd0 + 50.f) / (eqr0 + 50.f), 1.2f);
            as = (as < 3.f) ? 0.f : fminf(as, 12.f);
            acc1 += ad * as * w0;
        }
        if (has1) {
            float eqr1 = bpr1 * R1[k];
            float eqd1 = fp * D1[k];
            float dl = loudf(eqd1, th1, g1);
            float rl = loudf(eqr1, th1, g1);
            float di = dl - rl;
            float dz = 0.25f * fminf(dl, rl);
            float ad = fmaxf(fabsf(di) - dz, 0.f);
            float t2 = ad * w0;
            acc2 += t2 * t2;
            float as = __powf((eqd1 + 50.f) / (eqr1 + 50.f), 1.2f);
            as = (as < 3.f) ? 0.f : fminf(as, 12.f);
            acc1 += ad * as * w0;
        }
        acc2 = wredsum(acc2);
        acc1 = wredsum(acc1);
        if (lane == 0) {
            float symm = fmaxf(sqrtf(acc2 / wsum) * wsum, 1e-20f);
            float asym = fmaxf(acc1, 1e-20f);
            float h = __powf((TA[k] + 1e5f) * 1e-7f, 0.04f);
            g_symm[b][f] = fminf(symm / h, 45.f);
            g_asym[b][f] = fminf(asym / h, 45.f);
        }
    }
}

// ============================ psqm + mos =====================================
__global__ void k_psqm(float* __restrict__ out) {
    int b = blockIdx.x, t = threadIdx.x;   // 64 threads
    float accS = 0.f, accA = 0.f;
    if (t < 61) {
        int base = t * 10;
        float m6s = 0.f, m6a = 0.f;
        #pragma unroll
        for (int i = 0; i < 20; i++) {
            float xs = g_symm[b][base + i];
            float x2 = xs * xs;
            m6s += x2 * x2 * x2;
            float xa = g_asym[b][base + i];
            float y2 = xa * xa;
            m6a += y2 * y2 * y2;
        }
        accS = cbrtf(m6s * (1.f / 20.f));
        accA = cbrtf(m6a * (1.f / 20.f));
    }
    accS = wredsum(accS);
    accA = wredsum(accA);
    __shared__ float sS[2], sA[2];
    if ((t & 31) == 0) { sS[t >> 5] = accS; sA[t >> 5] = accA; }
    __syncthreads();
    if (t == 0) {
        float ds = sqrtf((sS[0] + sS[1]) / 61.f);
        float da = sqrtf((sA[0] + sA[1]) / 61.f);
        float mos = 4.5f - 0.1f * ds - 0.0309f * da;
        mos = 0.999f + 4.f / (1.f + expf(-1.3669f * mos + 3.8224f));
        out[b] = 0.5f * (4.5f - mos);
    }
}

// ============================ launch =========================================
extern "C" void kernel_launch(void* const* d_in, const int* in_sizes, int n_in,
                              void* d_out, int out_size) {
    const float* deg = (const float*)d_in[0];
    const float* ref = (const float*)d_in[1];
    float* out = (float*)d_out;

    k_init<<<1, 1024>>>();

    {   // IIR: 128 signals * 50 chunks = 6400 warps
        int warps = 2 * NBATCH * NCH;
        k_iir<<<warps * 32 / 256, 256>>>(deg, ref);
    }
    {   // spec: 2*64*78 warp-tasks, 8 warps/block
        int tasks = 2 * NBATCH * (NFRAMES / FPW);
        k_spec<<<tasks / 8, 256>>>();
    }
    {
        dim3 gs(NBATCH, NSLAB);
        k_tsum<<<gs, 256>>>();
    }
    {   // dist: 64*156 warp-strips of 4 frames
        int warps = NBATCH * (NFRAMES / DFR);
        k_dist<<<warps * 32 / 256, 256>>>();
    }
    k_psqm<<<NBATCH, 64>>>(out);
}